// round 3
// baseline (speedup 1.0000x reference)
#include <cuda_runtime.h>
#include <cstdint>

// ---------------- problem constants ----------------
#define BB   16
#define CC   256
#define HH   64
#define WW   64
#define NHH  8
#define DHH  64
#define CIN  260
#define DQKV 512
#define HWN  4096               // H*W
#define PLEN 128                // W+H logits per query
#define SCALE 0.08838834764831843f  // 1/sqrt(128)

// ---------------- device scratch (global .bss, allowed) ----------------
// each tensor: B * DQKV * H * W floats = 33,554,432 (134 MB)
#define TSZ ((size_t)BB * DQKV * HWN)
__device__ float g_Q [TSZ];
__device__ float g_K [TSZ];
__device__ float g_V [TSZ];
__device__ float g_QT[TSZ];
__device__ float g_KT[TSZ];
__device__ float g_VT[TSZ];
__device__ float g_A [TSZ];
__device__ float g_AT[TSZ];
// logits/probs: B * NH * H * W * 128 = 67,108,864 floats (268 MB)
__device__ float g_P [(size_t)BB * NHH * HH * WW * PLEN];

// =====================================================================
// Kernel 1: QKV projection GEMM.  out[b][m][p] = sum_c W[m][c]*xp[b][c][p] + bias[m]
// xp = concat(x, pos_emb) along channels (CIN = 260).
// Tiles: BM=128, BN=128, BK=8. 256 threads, 8x8 microtile each.
// grid: (N/128=32, 12, 16); blockIdx.y: [0..3]->Q tiles, [4..7]->K, [8..11]->V
// =====================================================================
__global__ __launch_bounds__(256) void qkv_gemm(
    const float* __restrict__ x, const float* __restrict__ pos,
    const float* __restrict__ Wq, const float* __restrict__ bq,
    const float* __restrict__ Wk, const float* __restrict__ bk,
    const float* __restrict__ Wv, const float* __restrict__ bv)
{
    int which = blockIdx.y >> 2;
    int mBlk  = (blockIdx.y & 3) * 128;
    int nBlk  = blockIdx.x * 128;
    int b     = blockIdx.z;
    const float* Wt   = (which == 0) ? Wq : (which == 1) ? Wk : Wv;
    const float* bias = (which == 0) ? bq : (which == 1) ? bk : bv;
    float*       out  = (which == 0) ? g_Q : (which == 1) ? g_K : g_V;

    __shared__ float As[8][132];   // [k][m], padded
    __shared__ float Bs[8][128];   // [k][n]

    int t  = threadIdx.x;
    int tx = t & 15, ty = t >> 4;
    float acc[8][8] = {};
    const float* xb = x + (size_t)b * (CC * HWN);

    for (int k0 = 0; k0 < CIN; k0 += 8) {
        // load A tile (W): 128x8, guarded for K remainder (260 % 8 == 4)
        #pragma unroll
        for (int r = 0; r < 4; r++) {
            int idx = r * 256 + t;
            int m = idx >> 3, k = idx & 7;
            float v = 0.0f;
            if (k0 + k < CIN) v = Wt[(size_t)(mBlk + m) * CIN + (k0 + k)];
            As[k][m] = v;
        }
        // load B tile (xp): 8x128, one float4 per thread
        {
            int kk = t >> 5;
            int n  = (t & 31) * 4;
            int kg = k0 + kk;
            float4 v = make_float4(0.f, 0.f, 0.f, 0.f);
            if (kg < CC)
                v = *(const float4*)(xb + (size_t)kg * HWN + nBlk + n);
            else if (kg < CIN)
                v = *(const float4*)(pos + (size_t)(kg - CC) * HWN + nBlk + n);
            *(float4*)&Bs[kk][n] = v;
        }
        __syncthreads();
        #pragma unroll
        for (int kk = 0; kk < 8; kk++) {
            float4 a0 = *(float4*)&As[kk][ty * 8];
            float4 a1 = *(float4*)&As[kk][ty * 8 + 4];
            float4 b0 = *(float4*)&Bs[kk][tx * 8];
            float4 b1 = *(float4*)&Bs[kk][tx * 8 + 4];
            float av[8] = {a0.x, a0.y, a0.z, a0.w, a1.x, a1.y, a1.z, a1.w};
            float bv2[8] = {b0.x, b0.y, b0.z, b0.w, b1.x, b1.y, b1.z, b1.w};
            #pragma unroll
            for (int i = 0; i < 8; i++)
                #pragma unroll
                for (int j = 0; j < 8; j++)
                    acc[i][j] = fmaf(av[i], bv2[j], acc[i][j]);
        }
        __syncthreads();
    }

    float* ob = out + (size_t)b * (DQKV * HWN);
    #pragma unroll
    for (int i = 0; i < 8; i++) {
        int m = mBlk + ty * 8 + i;
        float bi = bias[m];
        float4 o0 = make_float4(acc[i][0] + bi, acc[i][1] + bi, acc[i][2] + bi, acc[i][3] + bi);
        float4 o1 = make_float4(acc[i][4] + bi, acc[i][5] + bi, acc[i][6] + bi, acc[i][7] + bi);
        *(float4*)(ob + (size_t)m * HWN + nBlk + tx * 8)     = o0;
        *(float4*)(ob + (size_t)m * HWN + nBlk + tx * 8 + 4) = o1;
    }
}

// =====================================================================
// Kernel 2: transpose each 64x64 image of Q,K,V -> QT,KT,VT
// grid: (B*DQKV = 8192, 3)
// =====================================================================
__global__ __launch_bounds__(256) void transpose3_kernel()
{
    const float* src = (blockIdx.y == 0) ? g_Q : (blockIdx.y == 1) ? g_K : g_V;
    float*       dst = (blockIdx.y == 0) ? g_QT : (blockIdx.y == 1) ? g_KT : g_VT;
    size_t base = (size_t)blockIdx.x * HWN;
    __shared__ float sm[64][65];
    int t = threadIdx.x;
    #pragma unroll
    for (int r = 0; r < 16; r++) {
        int idx = r * 256 + t;
        sm[idx >> 6][idx & 63] = src[base + idx];
    }
    __syncthreads();
    #pragma unroll
    for (int r = 0; r < 16; r++) {
        int idx = r * 256 + t;
        dst[base + idx] = sm[idx & 63][idx >> 6];
    }
}

// =====================================================================
// Kernel 3: row logits. block (i, h, b). S[j][k] = sum_d Q[d,i,j]*K[d,i,k]
// writes g_P[b,h,i,j, 0..63]
// =====================================================================
__global__ __launch_bounds__(256) void logits_row_kernel()
{
    int i = blockIdx.x, h = blockIdx.y, b = blockIdx.z;
    __shared__ float qs[64][64];
    __shared__ float ks[64][64];
    size_t base = ((size_t)(b * DQKV + h * DHH)) * HWN + i * WW;
    int t = threadIdx.x;
    #pragma unroll
    for (int r = 0; r < 16; r++) {
        int idx = r * 256 + t;
        int d = idx >> 6, j = idx & 63;
        qs[d][j] = g_Q[base + (size_t)d * HWN + j];
        ks[d][j] = g_K[base + (size_t)d * HWN + j];
    }
    __syncthreads();
    int tx = t & 15, ty = t >> 4;
    float acc[4][4] = {};
    #pragma unroll
    for (int d = 0; d < 64; d++) {
        float4 q4 = *(float4*)&qs[d][ty * 4];
        float4 k4 = *(float4*)&ks[d][tx * 4];
        float qa[4] = {q4.x, q4.y, q4.z, q4.w};
        float ka[4] = {k4.x, k4.y, k4.z, k4.w};
        #pragma unroll
        for (int u = 0; u < 4; u++)
            #pragma unroll
            for (int v = 0; v < 4; v++)
                acc[u][v] = fmaf(qa[u], ka[v], acc[u][v]);
    }
    size_t pbase = (((size_t)((b * NHH + h) * HH + i)) * WW) * PLEN;
    #pragma unroll
    for (int u = 0; u < 4; u++) {
        int j = ty * 4 + u;
        float4 o = make_float4(acc[u][0] * SCALE, acc[u][1] * SCALE,
                               acc[u][2] * SCALE, acc[u][3] * SCALE);
        *(float4*)&g_P[pbase + (size_t)j * PLEN + tx * 4] = o;
    }
}

// =====================================================================
// Kernel 4: column logits. block (j, h, b). L[i][k] = sum_d Q[d,i,j]*K[d,k,j]
// reads QT/KT rows (contiguous), writes g_P[b,h,i,j, 64..127]
// =====================================================================
__global__ __launch_bounds__(256) void logits_col_kernel()
{
    int j = blockIdx.x, h = blockIdx.y, b = blockIdx.z;
    __shared__ float qs[64][64];   // qs[d][i] = Q[d,i,j]
    __shared__ float ks[64][64];   // ks[d][k] = K[d,k,j]
    size_t base = ((size_t)(b * DQKV + h * DHH)) * HWN + j * HH;
    int t = threadIdx.x;
    #pragma unroll
    for (int r = 0; r < 16; r++) {
        int idx = r * 256 + t;
        int d = idx >> 6, ii = idx & 63;
        qs[d][ii] = g_QT[base + (size_t)d * HWN + ii];
        ks[d][ii] = g_KT[base + (size_t)d * HWN + ii];
    }
    __syncthreads();
    int tx = t & 15, ty = t >> 4;
    float acc[4][4] = {};
    #pragma unroll
    for (int d = 0; d < 64; d++) {
        float4 q4 = *(float4*)&qs[d][ty * 4];
        float4 k4 = *(float4*)&ks[d][tx * 4];
        float qa[4] = {q4.x, q4.y, q4.z, q4.w};
        float ka[4] = {k4.x, k4.y, k4.z, k4.w};
        #pragma unroll
        for (int u = 0; u < 4; u++)
            #pragma unroll
            for (int v = 0; v < 4; v++)
                acc[u][v] = fmaf(qa[u], ka[v], acc[u][v]);
    }
    size_t pre = ((size_t)((b * NHH + h) * HH) * WW + j) * PLEN + 64;
    #pragma unroll
    for (int u = 0; u < 4; u++) {
        int i = ty * 4 + u;
        float4 o = make_float4(acc[u][0] * SCALE, acc[u][1] * SCALE,
                               acc[u][2] * SCALE, acc[u][3] * SCALE);
        *(float4*)&g_P[pre + (size_t)i * (WW * PLEN) + tx * 4] = o;
    }
}

// =====================================================================
// Kernel 5: softmax over 128 logits per query, in place. 1 warp per row.
// rows = B*NH*H*W = 524288; grid 65536 x 256 threads (8 warps)
// =====================================================================
__global__ __launch_bounds__(256) void softmax_kernel()
{
    size_t row = (size_t)blockIdx.x * 8 + (threadIdx.x >> 5);
    int lane = threadIdx.x & 31;
    float* p = g_P + row * PLEN + lane * 4;
    float4 v = *(float4*)p;
    float m = fmaxf(fmaxf(v.x, v.y), fmaxf(v.z, v.w));
    #pragma unroll
    for (int o = 16; o; o >>= 1) m = fmaxf(m, __shfl_xor_sync(0xffffffffu, m, o));
    v.x = __expf(v.x - m); v.y = __expf(v.y - m);
    v.z = __expf(v.z - m); v.w = __expf(v.w - m);
    float s = v.x + v.y + v.z + v.w;
    #pragma unroll
    for (int o = 16; o; o >>= 1) s += __shfl_xor_sync(0xffffffffu, s, o);
    float inv = 1.0f / s;
    v.x *= inv; v.y *= inv; v.z *= inv; v.w *= inv;
    *(float4*)p = v;
}

// =====================================================================
// Kernel 6: row attention. block (i,h,b): a_w[d][j] = sum_k p_w[j][k]*V[d][i][k]
// writes g_A
// =====================================================================
__global__ __launch_bounds__(256) void attn_row_kernel()
{
    int i = blockIdx.x, h = blockIdx.y, b = blockIdx.z;
    __shared__ float vsT[64][68];  // [k][d]
    __shared__ float psT[64][68];  // [k][j]
    size_t vbase = ((size_t)(b * DQKV + h * DHH)) * HWN + i * WW;
    size_t pbase = (((size_t)((b * NHH + h) * HH + i)) * WW) * PLEN;
    int t = threadIdx.x;
    #pragma unroll
    for (int r = 0; r < 16; r++) {
        int idx = r * 256 + t;
        int a = idx >> 6, k = idx & 63;
        vsT[k][a] = g_V[vbase + (size_t)a * HWN + k];         // a = d
        psT[k][a] = g_P[pbase + (size_t)a * PLEN + k];        // a = j (first 64 = p_w)
    }
    __syncthreads();
    int tx = t & 15, ty = t >> 4;
    float acc[4][4] = {};
    #pragma unroll
    for (int k = 0; k < 64; k++) {
        float4 v4 = *(float4*)&vsT[k][ty * 4];
        float4 p4 = *(float4*)&psT[k][tx * 4];
        float va[4] = {v4.x, v4.y, v4.z, v4.w};
        float pa[4] = {p4.x, p4.y, p4.z, p4.w};
        #pragma unroll
        for (int u = 0; u < 4; u++)
            #pragma unroll
            for (int v = 0; v < 4; v++)
                acc[u][v] = fmaf(va[u], pa[v], acc[u][v]);
    }
    #pragma unroll
    for (int u = 0; u < 4; u++) {
        int d = ty * 4 + u;
        float4 o = make_float4(acc[u][0], acc[u][1], acc[u][2], acc[u][3]);
        *(float4*)&g_A[vbase + (size_t)d * HWN + tx * 4] = o;
    }
}

// =====================================================================
// Kernel 7: column attention. block (j,h,b): a_h[d][i] = sum_k p_h[i][k]*V[d][k][j]
// reads VT rows, writes g_AT (transposed layout)
// =====================================================================
__global__ __launch_bounds__(256) void attn_col_kernel()
{
    int j = blockIdx.x, h = blockIdx.y, b = blockIdx.z;
    __shared__ float vsT[64][68];  // [k][d] = V[d,k,j]
    __shared__ float psT[64][68];  // [k][i]
    size_t vbase = ((size_t)(b * DQKV + h * DHH)) * HWN + j * HH;
    size_t pcol  = ((size_t)((b * NHH + h) * HH) * WW + j) * PLEN + 64;
    int t = threadIdx.x;
    #pragma unroll
    for (int r = 0; r < 16; r++) {
        int idx = r * 256 + t;
        int a = idx >> 6, k = idx & 63;
        vsT[k][a] = g_VT[vbase + (size_t)a * HWN + k];               // a = d
        psT[k][a] = g_P[pcol + (size_t)a * (WW * PLEN) + k];         // a = i
    }
    __syncthreads();
    int tx = t & 15, ty = t >> 4;
    float acc[4][4] = {};
    #pragma unroll
    for (int k = 0; k < 64; k++) {
        float4 v4 = *(float4*)&vsT[k][ty * 4];
        float4 p4 = *(float4*)&psT[k][tx * 4];
        float va[4] = {v4.x, v4.y, v4.z, v4.w};
        float pa[4] = {p4.x, p4.y, p4.z, p4.w};
        #pragma unroll
        for (int u = 0; u < 4; u++)
            #pragma unroll
            for (int v = 0; v < 4; v++)
                acc[u][v] = fmaf(va[u], pa[v], acc[u][v]);
    }
    #pragma unroll
    for (int u = 0; u < 4; u++) {
        int d = ty * 4 + u;
        float4 o = make_float4(acc[u][0], acc[u][1], acc[u][2], acc[u][3]);
        *(float4*)&g_AT[vbase + (size_t)d * HWN + tx * 4] = o;   // AT[ch][j][i]
    }
}

// =====================================================================
// Kernel 8: A[i][j] += AT[j][i] per (b,ch) image. grid 8192.
// =====================================================================
__global__ __launch_bounds__(256) void transpose_add_kernel()
{
    size_t base = (size_t)blockIdx.x * HWN;
    __shared__ float sm[64][65];
    int t = threadIdx.x;
    #pragma unroll
    for (int r = 0; r < 16; r++) {
        int idx = r * 256 + t;
        sm[idx >> 6][idx & 63] = g_AT[base + idx];
    }
    __syncthreads();
    #pragma unroll
    for (int r = 0; r < 16; r++) {
        int idx = r * 256 + t;
        g_A[base + idx] += sm[idx & 63][idx >> 6];
    }
}

// =====================================================================
// Kernel 9: output projection + residual.
// out[b][m][p] = x[b][m][p] + sum_c Wo[m][c]*A[b][c][p] + bo[m]
// M=256 (2 tiles), K=512, N=4096 per batch.
// =====================================================================
__global__ __launch_bounds__(256) void proj_gemm(
    const float* __restrict__ x, const float* __restrict__ Wo,
    const float* __restrict__ bo, float* __restrict__ out)
{
    int mBlk = blockIdx.y * 128;
    int nBlk = blockIdx.x * 128;
    int b    = blockIdx.z;

    __shared__ float As[8][132];
    __shared__ float Bs[8][128];

    int t  = threadIdx.x;
    int tx = t & 15, ty = t >> 4;
    float acc[8][8] = {};
    const float* Ab = g_A + (size_t)b * (DQKV * HWN);

    for (int k0 = 0; k0 < DQKV; k0 += 8) {
        #pragma unroll
        for (int r = 0; r < 4; r++) {
            int idx = r * 256 + t;
            int m = idx >> 3, k = idx & 7;
            As[k][m] = Wo[(size_t)(mBlk + m) * DQKV + k0 + k];
        }
        {
            int kk = t >> 5;
            int n  = (t & 31) * 4;
            *(float4*)&Bs[kk][n] =
                *(const float4*)(Ab + (size_t)(k0 + kk) * HWN + nBlk + n);
        }
        __syncthreads();
        #pragma unroll
        for (int kk = 0; kk < 8; kk++) {
            float4 a0 = *(float4*)&As[kk][ty * 8];
            float4 a1 = *(float4*)&As[kk][ty * 8 + 4];
            float4 b0 = *(float4*)&Bs[kk][tx * 8];
            float4 b1 = *(float4*)&Bs[kk][tx * 8 + 4];
            float av[8] = {a0.x, a0.y, a0.z, a0.w, a1.x, a1.y, a1.z, a1.w};
            float bv2[8] = {b0.x, b0.y, b0.z, b0.w, b1.x, b1.y, b1.z, b1.w};
            #pragma unroll
            for (int i = 0; i < 8; i++)
                #pragma unroll
                for (int j = 0; j < 8; j++)
                    acc[i][j] = fmaf(av[i], bv2[j], acc[i][j]);
        }
        __syncthreads();
    }

    #pragma unroll
    for (int i = 0; i < 8; i++) {
        int m = mBlk + ty * 8 + i;
        float bi = bo[m];
        size_t oidx = ((size_t)(b * CC + m)) * HWN + nBlk + tx * 8;
        float4 x0 = *(const float4*)(x + oidx);
        float4 x1 = *(const float4*)(x + oidx + 4);
        float4 o0 = make_float4(acc[i][0] + bi + x0.x, acc[i][1] + bi + x0.y,
                                acc[i][2] + bi + x0.z, acc[i][3] + bi + x0.w);
        float4 o1 = make_float4(acc[i][4] + bi + x1.x, acc[i][5] + bi + x1.y,
                                acc[i][6] + bi + x1.z, acc[i][7] + bi + x1.w);
        *(float4*)(out + oidx)     = o0;
        *(float4*)(out + oidx + 4) = o1;
    }
}

// =====================================================================
extern "C" void kernel_launch(void* const* d_in, const int* in_sizes, int n_in,
                              void* d_out, int out_size)
{
    const float* x   = (const float*)d_in[0];
    const float* pos = (const float*)d_in[1];
    const float* Wk  = (const float*)d_in[2];
    const float* bk  = (const float*)d_in[3];
    const float* Wq  = (const float*)d_in[4];
    const float* bq  = (const float*)d_in[5];
    const float* Wv  = (const float*)d_in[6];
    const float* bv  = (const float*)d_in[7];
    const float* Wo  = (const float*)d_in[8];
    const float* bo  = (const float*)d_in[9];
    float* out = (float*)d_out;

    qkv_gemm<<<dim3(32, 12, BB), 256>>>(x, pos, Wq, bq, Wk, bk, Wv, bv);
    transpose3_kernel<<<dim3(BB * DQKV, 3), 256>>>();
    logits_row_kernel<<<dim3(HH, NHH, BB), 256>>>();
    logits_col_kernel<<<dim3(WW, NHH, BB), 256>>>();
    softmax_kernel<<<65536, 256>>>();
    attn_row_kernel<<<dim3(HH, NHH, BB), 256>>>();
    attn_col_kernel<<<dim3(WW, NHH, BB), 256>>>();
    transpose_add_kernel<<<BB * DQKV, 256>>>();
    proj_gemm<<<dim3(32, 2, BB), 256>>>(x, Wo, bo, out);
}

// round 4
// speedup vs baseline: 1.0528x; 1.0528x over previous
#include <cuda_runtime.h>
#include <cstdint>

// ---------------- problem constants ----------------
#define BB   16
#define CC   256
#define HH   64
#define WW   64
#define NHH  8
#define DHH  64
#define CIN  260
#define DQKV 512
#define HWN  4096               // H*W
#define PLEN 128                // W+H logits per query
#define SCALE 0.08838834764831843f  // 1/sqrt(128)

typedef unsigned long long u64;

// ---------------- f32x2 packed-FMA helpers (FFMA2 path) ----------------
__device__ __forceinline__ u64 pk2(float x) {
    u64 r; asm("mov.b64 %0, {%1, %1};" : "=l"(r) : "f"(x)); return r;
}
__device__ __forceinline__ void fma2(u64 &d, u64 a, u64 b) {
    asm("fma.rn.f32x2 %0, %1, %2, %3;" : "=l"(d) : "l"(a), "l"(b), "l"(d));
}
__device__ __forceinline__ float2 up2(u64 v) {
    float lo, hi; asm("mov.b64 {%0, %1}, %2;" : "=f"(lo), "=f"(hi) : "l"(v));
    return make_float2(lo, hi);
}

// ---------------- device scratch (global .bss, allowed) ----------------
#define TSZ ((size_t)BB * DQKV * HWN)
__device__ float g_Q [TSZ];
__device__ float g_K [TSZ];
__device__ float g_V [TSZ];
__device__ float g_QT[TSZ];
__device__ float g_KT[TSZ];
__device__ float g_VT[TSZ];
__device__ float g_A [TSZ];
__device__ float g_AT[TSZ];
__device__ float g_P [(size_t)BB * NHH * HH * WW * PLEN];

// =====================================================================
// Kernel 1: QKV projection GEMM (f32x2 inner loop).
// out[b][m][p] = sum_c W[m][c]*xp[b][c][p] + bias[m]
// Tiles: BM=128, BN=128, BK=8. 256 threads, 8x(4x2) microtile each.
// =====================================================================
__global__ __launch_bounds__(256, 2) void qkv_gemm(
    const float* __restrict__ x, const float* __restrict__ pos,
    const float* __restrict__ Wq, const float* __restrict__ bq,
    const float* __restrict__ Wk, const float* __restrict__ bk,
    const float* __restrict__ Wv, const float* __restrict__ bv)
{
    int which = blockIdx.y >> 2;
    int mBlk  = (blockIdx.y & 3) * 128;
    int nBlk  = blockIdx.x * 128;
    int b     = blockIdx.z;
    const float* Wt   = (which == 0) ? Wq : (which == 1) ? Wk : Wv;
    const float* bias = (which == 0) ? bq : (which == 1) ? bk : bv;
    float*       out  = (which == 0) ? g_Q : (which == 1) ? g_K : g_V;

    __shared__ float As[8][132];   // [k][m], padded
    __shared__ float Bs[8][128];   // [k][n]

    int t  = threadIdx.x;
    int tx = t & 15, ty = t >> 4;
    u64 acc[8][4];
    #pragma unroll
    for (int i = 0; i < 8; i++)
        #pragma unroll
        for (int j = 0; j < 4; j++) acc[i][j] = 0ull;

    const float* xb = x + (size_t)b * (CC * HWN);

    for (int k0 = 0; k0 < CIN; k0 += 8) {
        #pragma unroll
        for (int r = 0; r < 4; r++) {
            int idx = r * 256 + t;
            int m = idx >> 3, k = idx & 7;
            float v = 0.0f;
            if (k0 + k < CIN) v = Wt[(size_t)(mBlk + m) * CIN + (k0 + k)];
            As[k][m] = v;
        }
        {
            int kk = t >> 5;
            int n  = (t & 31) * 4;
            int kg = k0 + kk;
            float4 v = make_float4(0.f, 0.f, 0.f, 0.f);
            if (kg < CC)
                v = *(const float4*)(xb + (size_t)kg * HWN + nBlk + n);
            else if (kg < CIN)
                v = *(const float4*)(pos + (size_t)(kg - CC) * HWN + nBlk + n);
            *(float4*)&Bs[kk][n] = v;
        }
        __syncthreads();
        #pragma unroll
        for (int kk = 0; kk < 8; kk++) {
            float4 a0 = *(float4*)&As[kk][ty * 8];
            float4 a1 = *(float4*)&As[kk][ty * 8 + 4];
            u64 ap[8] = {pk2(a0.x), pk2(a0.y), pk2(a0.z), pk2(a0.w),
                         pk2(a1.x), pk2(a1.y), pk2(a1.z), pk2(a1.w)};
            const u64* bp = (const u64*)&Bs[kk][tx * 8];   // 4 packed n-pairs
            u64 b0 = bp[0], b1 = bp[1], b2 = bp[2], b3 = bp[3];
            #pragma unroll
            for (int i = 0; i < 8; i++) {
                fma2(acc[i][0], ap[i], b0);
                fma2(acc[i][1], ap[i], b1);
                fma2(acc[i][2], ap[i], b2);
                fma2(acc[i][3], ap[i], b3);
            }
        }
        __syncthreads();
    }

    float* ob = out + (size_t)b * (DQKV * HWN);
    #pragma unroll
    for (int i = 0; i < 8; i++) {
        int m = mBlk + ty * 8 + i;
        float bi = bias[m];
        float2 p0 = up2(acc[i][0]), p1 = up2(acc[i][1]);
        float2 p2 = up2(acc[i][2]), p3 = up2(acc[i][3]);
        float4 o0 = make_float4(p0.x + bi, p0.y + bi, p1.x + bi, p1.y + bi);
        float4 o1 = make_float4(p2.x + bi, p2.y + bi, p3.x + bi, p3.y + bi);
        *(float4*)(ob + (size_t)m * HWN + nBlk + tx * 8)     = o0;
        *(float4*)(ob + (size_t)m * HWN + nBlk + tx * 8 + 4) = o1;
    }
}

// =====================================================================
// Kernel 2: transpose each 64x64 image of Q,K,V -> QT,KT,VT
// =====================================================================
__global__ __launch_bounds__(256) void transpose3_kernel()
{
    const float* src = (blockIdx.y == 0) ? g_Q : (blockIdx.y == 1) ? g_K : g_V;
    float*       dst = (blockIdx.y == 0) ? g_QT : (blockIdx.y == 1) ? g_KT : g_VT;
    size_t base = (size_t)blockIdx.x * HWN;
    __shared__ float sm[64][65];
    int t = threadIdx.x;
    #pragma unroll
    for (int r = 0; r < 16; r++) {
        int idx = r * 256 + t;
        sm[idx >> 6][idx & 63] = src[base + idx];
    }
    __syncthreads();
    #pragma unroll
    for (int r = 0; r < 16; r++) {
        int idx = r * 256 + t;
        dst[base + idx] = sm[idx & 63][idx >> 6];
    }
}

// =====================================================================
// Kernel 3: row logits (f32x2). block (i, h, b).
// =====================================================================
__global__ __launch_bounds__(256) void logits_row_kernel()
{
    int i = blockIdx.x, h = blockIdx.y, b = blockIdx.z;
    __shared__ float qs[64][64];
    __shared__ float ks[64][64];
    size_t base = ((size_t)(b * DQKV + h * DHH)) * HWN + i * WW;
    int t = threadIdx.x;
    #pragma unroll
    for (int r = 0; r < 16; r++) {
        int idx = r * 256 + t;
        int d = idx >> 6, j = idx & 63;
        qs[d][j] = g_Q[base + (size_t)d * HWN + j];
        ks[d][j] = g_K[base + (size_t)d * HWN + j];
    }
    __syncthreads();
    int tx = t & 15, ty = t >> 4;
    u64 acc[4][2];
    #pragma unroll
    for (int u = 0; u < 4; u++) { acc[u][0] = 0ull; acc[u][1] = 0ull; }
    #pragma unroll
    for (int d = 0; d < 64; d++) {
        float4 q4 = *(float4*)&qs[d][ty * 4];
        const u64* kp = (const u64*)&ks[d][tx * 4];
        u64 k0 = kp[0], k1 = kp[1];
        u64 qa[4] = {pk2(q4.x), pk2(q4.y), pk2(q4.z), pk2(q4.w)};
        #pragma unroll
        for (int u = 0; u < 4; u++) {
            fma2(acc[u][0], qa[u], k0);
            fma2(acc[u][1], qa[u], k1);
        }
    }
    size_t pbase = (((size_t)((b * NHH + h) * HH + i)) * WW) * PLEN;
    #pragma unroll
    for (int u = 0; u < 4; u++) {
        int j = ty * 4 + u;
        float2 p0 = up2(acc[u][0]), p1 = up2(acc[u][1]);
        float4 o = make_float4(p0.x * SCALE, p0.y * SCALE, p1.x * SCALE, p1.y * SCALE);
        *(float4*)&g_P[pbase + (size_t)j * PLEN + tx * 4] = o;
    }
}

// =====================================================================
// Kernel 4: column logits (f32x2). block (j, h, b).
// =====================================================================
__global__ __launch_bounds__(256) void logits_col_kernel()
{
    int j = blockIdx.x, h = blockIdx.y, b = blockIdx.z;
    __shared__ float qs[64][64];
    __shared__ float ks[64][64];
    size_t base = ((size_t)(b * DQKV + h * DHH)) * HWN + j * HH;
    int t = threadIdx.x;
    #pragma unroll
    for (int r = 0; r < 16; r++) {
        int idx = r * 256 + t;
        int d = idx >> 6, ii = idx & 63;
        qs[d][ii] = g_QT[base + (size_t)d * HWN + ii];
        ks[d][ii] = g_KT[base + (size_t)d * HWN + ii];
    }
    __syncthreads();
    int tx = t & 15, ty = t >> 4;
    u64 acc[4][2];
    #pragma unroll
    for (int u = 0; u < 4; u++) { acc[u][0] = 0ull; acc[u][1] = 0ull; }
    #pragma unroll
    for (int d = 0; d < 64; d++) {
        float4 q4 = *(float4*)&qs[d][ty * 4];
        const u64* kp = (const u64*)&ks[d][tx * 4];
        u64 k0 = kp[0], k1 = kp[1];
        u64 qa[4] = {pk2(q4.x), pk2(q4.y), pk2(q4.z), pk2(q4.w)};
        #pragma unroll
        for (int u = 0; u < 4; u++) {
            fma2(acc[u][0], qa[u], k0);
            fma2(acc[u][1], qa[u], k1);
        }
    }
    size_t pre = ((size_t)((b * NHH + h) * HH) * WW + j) * PLEN + 64;
    #pragma unroll
    for (int u = 0; u < 4; u++) {
        int i = ty * 4 + u;
        float2 p0 = up2(acc[u][0]), p1 = up2(acc[u][1]);
        float4 o = make_float4(p0.x * SCALE, p0.y * SCALE, p1.x * SCALE, p1.y * SCALE);
        *(float4*)&g_P[pre + (size_t)i * (WW * PLEN) + tx * 4] = o;
    }
}

// =====================================================================
// Kernel 5: softmax over 128 logits per query, in place.
// =====================================================================
__global__ __launch_bounds__(256) void softmax_kernel()
{
    size_t row = (size_t)blockIdx.x * 8 + (threadIdx.x >> 5);
    int lane = threadIdx.x & 31;
    float* p = g_P + row * PLEN + lane * 4;
    float4 v = *(float4*)p;
    float m = fmaxf(fmaxf(v.x, v.y), fmaxf(v.z, v.w));
    #pragma unroll
    for (int o = 16; o; o >>= 1) m = fmaxf(m, __shfl_xor_sync(0xffffffffu, m, o));
    v.x = __expf(v.x - m); v.y = __expf(v.y - m);
    v.z = __expf(v.z - m); v.w = __expf(v.w - m);
    float s = v.x + v.y + v.z + v.w;
    #pragma unroll
    for (int o = 16; o; o >>= 1) s += __shfl_xor_sync(0xffffffffu, s, o);
    float inv = 1.0f / s;
    v.x *= inv; v.y *= inv; v.z *= inv; v.w *= inv;
    *(float4*)p = v;
}

// =====================================================================
// Kernel 6: row attention (f32x2). block (i,h,b).
// =====================================================================
__global__ __launch_bounds__(256) void attn_row_kernel()
{
    int i = blockIdx.x, h = blockIdx.y, b = blockIdx.z;
    __shared__ float vsT[64][68];  // [k][d]
    __shared__ float psT[64][68];  // [k][j]
    size_t vbase = ((size_t)(b * DQKV + h * DHH)) * HWN + i * WW;
    size_t pbase = (((size_t)((b * NHH + h) * HH + i)) * WW) * PLEN;
    int t = threadIdx.x;
    #pragma unroll
    for (int r = 0; r < 16; r++) {
        int idx = r * 256 + t;
        int a = idx >> 6, k = idx & 63;
        vsT[k][a] = g_V[vbase + (size_t)a * HWN + k];
        psT[k][a] = g_P[pbase + (size_t)a * PLEN + k];
    }
    __syncthreads();
    int tx = t & 15, ty = t >> 4;
    u64 acc[4][2];
    #pragma unroll
    for (int u = 0; u < 4; u++) { acc[u][0] = 0ull; acc[u][1] = 0ull; }
    #pragma unroll
    for (int k = 0; k < 64; k++) {
        float4 v4 = *(float4*)&vsT[k][ty * 4];
        const u64* pp = (const u64*)&psT[k][tx * 4];
        u64 p0 = pp[0], p1 = pp[1];
        u64 va[4] = {pk2(v4.x), pk2(v4.y), pk2(v4.z), pk2(v4.w)};
        #pragma unroll
        for (int u = 0; u < 4; u++) {
            fma2(acc[u][0], va[u], p0);
            fma2(acc[u][1], va[u], p1);
        }
    }
    #pragma unroll
    for (int u = 0; u < 4; u++) {
        int d = ty * 4 + u;
        float2 a0 = up2(acc[u][0]), a1 = up2(acc[u][1]);
        float4 o = make_float4(a0.x, a0.y, a1.x, a1.y);
        *(float4*)&g_A[vbase + (size_t)d * HWN + tx * 4] = o;
    }
}

// =====================================================================
// Kernel 7: column attention (f32x2). block (j,h,b). writes g_AT.
// =====================================================================
__global__ __launch_bounds__(256) void attn_col_kernel()
{
    int j = blockIdx.x, h = blockIdx.y, b = blockIdx.z;
    __shared__ float vsT[64][68];  // [k][d]
    __shared__ float psT[64][68];  // [k][i]
    size_t vbase = ((size_t)(b * DQKV + h * DHH)) * HWN + j * HH;
    size_t pcol  = ((size_t)((b * NHH + h) * HH) * WW + j) * PLEN + 64;
    int t = threadIdx.x;
    #pragma unroll
    for (int r = 0; r < 16; r++) {
        int idx = r * 256 + t;
        int a = idx >> 6, k = idx & 63;
        vsT[k][a] = g_VT[vbase + (size_t)a * HWN + k];
        psT[k][a] = g_P[pcol + (size_t)a * (WW * PLEN) + k];
    }
    __syncthreads();
    int tx = t & 15, ty = t >> 4;
    u64 acc[4][2];
    #pragma unroll
    for (int u = 0; u < 4; u++) { acc[u][0] = 0ull; acc[u][1] = 0ull; }
    #pragma unroll
    for (int k = 0; k < 64; k++) {
        float4 v4 = *(float4*)&vsT[k][ty * 4];
        const u64* pp = (const u64*)&psT[k][tx * 4];
        u64 p0 = pp[0], p1 = pp[1];
        u64 va[4] = {pk2(v4.x), pk2(v4.y), pk2(v4.z), pk2(v4.w)};
        #pragma unroll
        for (int u = 0; u < 4; u++) {
            fma2(acc[u][0], va[u], p0);
            fma2(acc[u][1], va[u], p1);
        }
    }
    #pragma unroll
    for (int u = 0; u < 4; u++) {
        int d = ty * 4 + u;
        float2 a0 = up2(acc[u][0]), a1 = up2(acc[u][1]);
        float4 o = make_float4(a0.x, a0.y, a1.x, a1.y);
        *(float4*)&g_AT[vbase + (size_t)d * HWN + tx * 4] = o;
    }
}

// =====================================================================
// Kernel 8: A[i][j] += AT[j][i] per (b,ch) image.
// =====================================================================
__global__ __launch_bounds__(256) void transpose_add_kernel()
{
    size_t base = (size_t)blockIdx.x * HWN;
    __shared__ float sm[64][65];
    int t = threadIdx.x;
    #pragma unroll
    for (int r = 0; r < 16; r++) {
        int idx = r * 256 + t;
        sm[idx >> 6][idx & 63] = g_AT[base + idx];
    }
    __syncthreads();
    #pragma unroll
    for (int r = 0; r < 16; r++) {
        int idx = r * 256 + t;
        g_A[base + idx] += sm[idx & 63][idx >> 6];
    }
}

// =====================================================================
// Kernel 9: output projection + residual (f32x2).
// =====================================================================
__global__ __launch_bounds__(256, 2) void proj_gemm(
    const float* __restrict__ x, const float* __restrict__ Wo,
    const float* __restrict__ bo, float* __restrict__ out)
{
    int mBlk = blockIdx.y * 128;
    int nBlk = blockIdx.x * 128;
    int b    = blockIdx.z;

    __shared__ float As[8][132];
    __shared__ float Bs[8][128];

    int t  = threadIdx.x;
    int tx = t & 15, ty = t >> 4;
    u64 acc[8][4];
    #pragma unroll
    for (int i = 0; i < 8; i++)
        #pragma unroll
        for (int j = 0; j < 4; j++) acc[i][j] = 0ull;

    const float* Ab = g_A + (size_t)b * (DQKV * HWN);

    for (int k0 = 0; k0 < DQKV; k0 += 8) {
        #pragma unroll
        for (int r = 0; r < 4; r++) {
            int idx = r * 256 + t;
            int m = idx >> 3, k = idx & 7;
            As[k][m] = Wo[(size_t)(mBlk + m) * DQKV + k0 + k];
        }
        {
            int kk = t >> 5;
            int n  = (t & 31) * 4;
            *(float4*)&Bs[kk][n] =
                *(const float4*)(Ab + (size_t)(k0 + kk) * HWN + nBlk + n);
        }
        __syncthreads();
        #pragma unroll
        for (int kk = 0; kk < 8; kk++) {
            float4 a0 = *(float4*)&As[kk][ty * 8];
            float4 a1 = *(float4*)&As[kk][ty * 8 + 4];
            u64 ap[8] = {pk2(a0.x), pk2(a0.y), pk2(a0.z), pk2(a0.w),
                         pk2(a1.x), pk2(a1.y), pk2(a1.z), pk2(a1.w)};
            const u64* bp = (const u64*)&Bs[kk][tx * 8];
            u64 b0 = bp[0], b1 = bp[1], b2 = bp[2], b3 = bp[3];
            #pragma unroll
            for (int i = 0; i < 8; i++) {
                fma2(acc[i][0], ap[i], b0);
                fma2(acc[i][1], ap[i], b1);
                fma2(acc[i][2], ap[i], b2);
                fma2(acc[i][3], ap[i], b3);
            }
        }
        __syncthreads();
    }

    #pragma unroll
    for (int i = 0; i < 8; i++) {
        int m = mBlk + ty * 8 + i;
        float bi = bo[m];
        size_t oidx = ((size_t)(b * CC + m)) * HWN + nBlk + tx * 8;
        float4 x0 = *(const float4*)(x + oidx);
        float4 x1 = *(const float4*)(x + oidx + 4);
        float2 p0 = up2(acc[i][0]), p1 = up2(acc[i][1]);
        float2 p2 = up2(acc[i][2]), p3 = up2(acc[i][3]);
        float4 o0 = make_float4(p0.x + bi + x0.x, p0.y + bi + x0.y,
                                p1.x + bi + x0.z, p1.y + bi + x0.w);
        float4 o1 = make_float4(p2.x + bi + x1.x, p2.y + bi + x1.y,
                                p3.x + bi + x1.z, p3.y + bi + x1.w);
        *(float4*)(out + oidx)     = o0;
        *(float4*)(out + oidx + 4) = o1;
    }
}

// =====================================================================
extern "C" void kernel_launch(void* const* d_in, const int* in_sizes, int n_in,
                              void* d_out, int out_size)
{
    const float* x   = (const float*)d_in[0];
    const float* pos = (const float*)d_in[1];
    const float* Wk  = (const float*)d_in[2];
    const float* bk  = (const float*)d_in[3];
    const float* Wq  = (const float*)d_in[4];
    const float* bq  = (const float*)d_in[5];
    const float* Wv  = (const float*)d_in[6];
    const float* bv  = (const float*)d_in[7];
    const float* Wo  = (const float*)d_in[8];
    const float* bo  = (const float*)d_in[9];
    float* out = (float*)d_out;

    qkv_gemm<<<dim3(32, 12, BB), 256>>>(x, pos, Wq, bq, Wk, bk, Wv, bv);
    transpose3_kernel<<<dim3(BB * DQKV, 3), 256>>>();
    logits_row_kernel<<<dim3(HH, NHH, BB), 256>>>();
    logits_col_kernel<<<dim3(WW, NHH, BB), 256>>>();
    softmax_kernel<<<65536, 256>>>();
    attn_row_kernel<<<dim3(HH, NHH, BB), 256>>>();
    attn_col_kernel<<<dim3(WW, NHH, BB), 256>>>();
    transpose_add_kernel<<<BB * DQKV, 256>>>();
    proj_gemm<<<dim3(32, 2, BB), 256>>>(x, Wo, bo, out);
}

// round 8
// speedup vs baseline: 1.0637x; 1.0104x over previous
#include <cuda_runtime.h>
#include <cstdint>

// ---------------- problem constants ----------------
#define BB   16
#define CC   256
#define HH   64
#define WW   64
#define NHH  8
#define DHH  64
#define CIN  260
#define DQKV 512
#define HWN  4096               // H*W
#define PLEN 128                // W+H logits per query
#define SCALE 0.08838834764831843f  // 1/sqrt(128)

typedef unsigned long long u64;

// ---------------- f32x2 packed-FMA helpers (FFMA2 path) ----------------
__device__ __forceinline__ u64 pk2(float x) {
    u64 r; asm("mov.b64 %0, {%1, %1};" : "=l"(r) : "f"(x)); return r;
}
__device__ __forceinline__ void fma2(u64 &d, u64 a, u64 b) {
    asm("fma.rn.f32x2 %0, %1, %2, %3;" : "=l"(d) : "l"(a), "l"(b), "l"(d));
}
__device__ __forceinline__ float2 up2(u64 v) {
    float lo, hi; asm("mov.b64 {%0, %1}, %2;" : "=f"(lo), "=f"(hi) : "l"(v));
    return make_float2(lo, hi);
}

// ---------------- device scratch (global .bss, allowed) ----------------
#define TSZ ((size_t)BB * DQKV * HWN)
__device__ float g_Q [TSZ];
__device__ float g_K [TSZ];
__device__ float g_V [TSZ];
__device__ float g_QT[TSZ];
__device__ float g_KT[TSZ];
__device__ float g_VT[TSZ];
__device__ float g_A [TSZ];
__device__ float g_AT[TSZ];
__device__ float g_P [(size_t)BB * NHH * HH * WW * PLEN];

// =====================================================================
// Kernel 1: QKV projection GEMM — double-buffered smem + reg prefetch.
// BM=128, BN=128, BK=8; 256 threads, 8x8 microtile (f32x2).
// =====================================================================
__global__ __launch_bounds__(256, 2) void qkv_gemm(
    const float* __restrict__ x, const float* __restrict__ pos,
    const float* __restrict__ Wq, const float* __restrict__ bq,
    const float* __restrict__ Wk, const float* __restrict__ bk,
    const float* __restrict__ Wv, const float* __restrict__ bv)
{
    int which = blockIdx.y >> 2;
    int mBlk  = (blockIdx.y & 3) * 128;
    int nBlk  = blockIdx.x * 128;
    int b     = blockIdx.z;
    const float* Wt   = (which == 0) ? Wq : (which == 1) ? Wk : Wv;
    const float* bias = (which == 0) ? bq : (which == 1) ? bk : bv;
    float*       out  = (which == 0) ? g_Q : (which == 1) ? g_K : g_V;

    __shared__ float As[2][8][132];   // [buf][k][m]
    __shared__ float Bs[2][8][128];   // [buf][k][n]

    int t  = threadIdx.x;
    int tx = t & 15, ty = t >> 4;
    const float* xb = x + (size_t)b * (CC * HWN);

    int aM[4], aK[4];
    #pragma unroll
    for (int r = 0; r < 4; r++) { int idx = r * 256 + t; aM[r] = idx >> 3; aK[r] = idx & 7; }
    int bK = t >> 5;
    int bN = (t & 31) * 4;

    u64 acc[8][4];
    #pragma unroll
    for (int i = 0; i < 8; i++)
        #pragma unroll
        for (int j = 0; j < 4; j++) acc[i][j] = 0ull;

    // ---- prologue: fetch tile 0 ----
    float aPf[4]; float4 bPf;
    #pragma unroll
    for (int r = 0; r < 4; r++)
        aPf[r] = Wt[(size_t)(mBlk + aM[r]) * CIN + aK[r]];
    bPf = *(const float4*)(xb + (size_t)bK * HWN + nBlk + bN);
    #pragma unroll
    for (int r = 0; r < 4; r++) As[0][aK[r]][aM[r]] = aPf[r];
    *(float4*)&Bs[0][bK][bN] = bPf;
    __syncthreads();

    int buf = 0;
    for (int k0 = 0; k0 < CIN; k0 += 8) {
        int k0n = k0 + 8;
        bool more = (k0n < CIN);
        if (more) {
            #pragma unroll
            for (int r = 0; r < 4; r++) {
                float v = 0.0f;
                int kg = k0n + aK[r];
                if (kg < CIN) v = Wt[(size_t)(mBlk + aM[r]) * CIN + kg];
                aPf[r] = v;
            }
            int kg = k0n + bK;
            float4 v = make_float4(0.f, 0.f, 0.f, 0.f);
            if (kg < CC)
                v = *(const float4*)(xb + (size_t)kg * HWN + nBlk + bN);
            else if (kg < CIN)
                v = *(const float4*)(pos + (size_t)(kg - CC) * HWN + nBlk + bN);
            bPf = v;
        }
        #pragma unroll
        for (int kk = 0; kk < 8; kk++) {
            float4 a0 = *(float4*)&As[buf][kk][ty * 8];
            float4 a1 = *(float4*)&As[buf][kk][ty * 8 + 4];
            u64 ap[8] = {pk2(a0.x), pk2(a0.y), pk2(a0.z), pk2(a0.w),
                         pk2(a1.x), pk2(a1.y), pk2(a1.z), pk2(a1.w)};
            const u64* bp = (const u64*)&Bs[buf][kk][tx * 8];
            u64 b0 = bp[0], b1 = bp[1], b2 = bp[2], b3 = bp[3];
            #pragma unroll
            for (int i = 0; i < 8; i++) {
                fma2(acc[i][0], ap[i], b0);
                fma2(acc[i][1], ap[i], b1);
                fma2(acc[i][2], ap[i], b2);
                fma2(acc[i][3], ap[i], b3);
            }
        }
        if (more) {
            #pragma unroll
            for (int r = 0; r < 4; r++) As[buf ^ 1][aK[r]][aM[r]] = aPf[r];
            *(float4*)&Bs[buf ^ 1][bK][bN] = bPf;
            __syncthreads();
            buf ^= 1;
        }
    }

    float* ob = out + (size_t)b * (DQKV * HWN);
    #pragma unroll
    for (int i = 0; i < 8; i++) {
        int m = mBlk + ty * 8 + i;
        float bi = bias[m];
        float2 p0 = up2(acc[i][0]), p1 = up2(acc[i][1]);
        float2 p2 = up2(acc[i][2]), p3 = up2(acc[i][3]);
        float4 o0 = make_float4(p0.x + bi, p0.y + bi, p1.x + bi, p1.y + bi);
        float4 o1 = make_float4(p2.x + bi, p2.y + bi, p3.x + bi, p3.y + bi);
        *(float4*)(ob + (size_t)m * HWN + nBlk + tx * 8)     = o0;
        *(float4*)(ob + (size_t)m * HWN + nBlk + tx * 8 + 4) = o1;
    }
}

// =====================================================================
// Kernel 2: transpose each 64x64 image of Q,K,V -> QT,KT,VT
// =====================================================================
__global__ __launch_bounds__(256) void transpose3_kernel()
{
    const float* src = (blockIdx.y == 0) ? g_Q : (blockIdx.y == 1) ? g_K : g_V;
    float*       dst = (blockIdx.y == 0) ? g_QT : (blockIdx.y == 1) ? g_KT : g_VT;
    size_t base = (size_t)blockIdx.x * HWN;
    __shared__ float sm[64][65];
    int t = threadIdx.x;
    #pragma unroll
    for (int r = 0; r < 16; r++) {
        int idx = r * 256 + t;
        sm[idx >> 6][idx & 63] = src[base + idx];
    }
    __syncthreads();
    #pragma unroll
    for (int r = 0; r < 16; r++) {
        int idx = r * 256 + t;
        dst[base + idx] = sm[idx & 63][idx >> 6];
    }
}

// =====================================================================
// Logits core: 64 threads, 8x8 per-thread tile over a 64x64x64 product.
// S[j][k] = sum_d qs[d][j] * ks[d][k]
// =====================================================================
__device__ __forceinline__ void logits_core(
    const float* __restrict__ qg, const float* __restrict__ kg_,
    float* __restrict__ outp, size_t outRowStride)
{
    __shared__ float qs[64][64];
    __shared__ float ks[64][64];
    int t = threadIdx.x;
    #pragma unroll
    for (int r = 0; r < 16; r++) {
        int idx = (r * 64 + t) * 4;
        int d = idx >> 6, j = idx & 63;
        *(float4*)&qs[d][j] = *(const float4*)(qg + (size_t)d * HWN + j);
        *(float4*)&ks[d][j] = *(const float4*)(kg_ + (size_t)d * HWN + j);
    }
    __syncthreads();
    int tx = t & 7, ty = t >> 3;
    u64 acc[8][4];
    #pragma unroll
    for (int u = 0; u < 8; u++)
        #pragma unroll
        for (int v = 0; v < 4; v++) acc[u][v] = 0ull;
    #pragma unroll
    for (int d = 0; d < 64; d++) {
        float4 q0 = *(float4*)&qs[d][ty * 8];
        float4 q1 = *(float4*)&qs[d][ty * 8 + 4];
        u64 qa[8] = {pk2(q0.x), pk2(q0.y), pk2(q0.z), pk2(q0.w),
                     pk2(q1.x), pk2(q1.y), pk2(q1.z), pk2(q1.w)};
        const u64* kp = (const u64*)&ks[d][tx * 8];
        u64 k0 = kp[0], k1 = kp[1], k2 = kp[2], k3 = kp[3];
        #pragma unroll
        for (int u = 0; u < 8; u++) {
            fma2(acc[u][0], qa[u], k0);
            fma2(acc[u][1], qa[u], k1);
            fma2(acc[u][2], qa[u], k2);
            fma2(acc[u][3], qa[u], k3);
        }
    }
    #pragma unroll
    for (int u = 0; u < 8; u++) {
        int j = ty * 8 + u;
        float2 p0 = up2(acc[u][0]), p1 = up2(acc[u][1]);
        float2 p2 = up2(acc[u][2]), p3 = up2(acc[u][3]);
        float4 o0 = make_float4(p0.x * SCALE, p0.y * SCALE, p1.x * SCALE, p1.y * SCALE);
        float4 o1 = make_float4(p2.x * SCALE, p2.y * SCALE, p3.x * SCALE, p3.y * SCALE);
        *(float4*)(outp + (size_t)j * outRowStride + tx * 8)     = o0;
        *(float4*)(outp + (size_t)j * outRowStride + tx * 8 + 4) = o1;
    }
}

// Kernel 3: row logits. block (i, h, b), 64 threads.
__global__ __launch_bounds__(64) void logits_row_kernel()
{
    int i = blockIdx.x, h = blockIdx.y, b = blockIdx.z;
    size_t base  = ((size_t)(b * DQKV + h * DHH)) * HWN + i * WW;
    size_t pbase = (((size_t)((b * NHH + h) * HH + i)) * WW) * PLEN;
    logits_core(g_Q + base, g_K + base, g_P + pbase, PLEN);
}

// Kernel 4: column logits. block (j, h, b), 64 threads.
__global__ __launch_bounds__(64) void logits_col_kernel()
{
    int j = blockIdx.x, h = blockIdx.y, b = blockIdx.z;
    size_t base = ((size_t)(b * DQKV + h * DHH)) * HWN + j * HH;
    size_t pre  = ((size_t)((b * NHH + h) * HH) * WW + j) * PLEN + 64;
    logits_core(g_QT + base, g_KT + base, g_P + pre, (size_t)WW * PLEN);
}

// =====================================================================
// Kernel 5: softmax over 128 logits per query, in place.
// =====================================================================
__global__ __launch_bounds__(256) void softmax_kernel()
{
    size_t row = (size_t)blockIdx.x * 8 + (threadIdx.x >> 5);
    int lane = threadIdx.x & 31;
    float* p = g_P + row * PLEN + lane * 4;
    float4 v = *(float4*)p;
    float m = fmaxf(fmaxf(v.x, v.y), fmaxf(v.z, v.w));
    #pragma unroll
    for (int o = 16; o; o >>= 1) m = fmaxf(m, __shfl_xor_sync(0xffffffffu, m, o));
    v.x = __expf(v.x - m); v.y = __expf(v.y - m);
    v.z = __expf(v.z - m); v.w = __expf(v.w - m);
    float s = v.x + v.y + v.z + v.w;
    #pragma unroll
    for (int o = 16; o; o >>= 1) s += __shfl_xor_sync(0xffffffffu, s, o);
    float inv = 1.0f / s;
    v.x *= inv; v.y *= inv; v.z *= inv; v.w *= inv;
    *(float4*)p = v;
}

// =====================================================================
// Attention core: 64 threads, 8x8 tile. out[d][c] = sum_k vsT[k][d]*psT[k][c]
// vsT/psT filled transposed from row-major sources.
// =====================================================================
__device__ __forceinline__ void attn_core(
    const float* __restrict__ vg, const float* __restrict__ pg,
    size_t pRowStride, float* __restrict__ outp)
{
    __shared__ float vsT[64][68];  // [k][d]
    __shared__ float psT[64][68];  // [k][c]
    int t = threadIdx.x;
    #pragma unroll
    for (int r = 0; r < 16; r++) {
        int idx = (r * 64 + t) * 4;
        int row = idx >> 6, k = idx & 63;
        float4 v = *(const float4*)(vg + (size_t)row * HWN + k);
        vsT[k][row] = v.x; vsT[k + 1][row] = v.y;
        vsT[k + 2][row] = v.z; vsT[k + 3][row] = v.w;
        float4 p = *(const float4*)(pg + (size_t)row * pRowStride + k);
        psT[k][row] = p.x; psT[k + 1][row] = p.y;
        psT[k + 2][row] = p.z; psT[k + 3][row] = p.w;
    }
    __syncthreads();
    int tx = t & 7, ty = t >> 3;
    u64 acc[8][4];
    #pragma unroll
    for (int u = 0; u < 8; u++)
        #pragma unroll
        for (int v = 0; v < 4; v++) acc[u][v] = 0ull;
    #pragma unroll
    for (int k = 0; k < 64; k++) {
        float4 v0 = *(float4*)&vsT[k][ty * 8];
        float4 v1 = *(float4*)&vsT[k][ty * 8 + 4];
        u64 va[8] = {pk2(v0.x), pk2(v0.y), pk2(v0.z), pk2(v0.w),
                     pk2(v1.x), pk2(v1.y), pk2(v1.z), pk2(v1.w)};
        const u64* pp = (const u64*)&psT[k][tx * 8];
        u64 p0 = pp[0], p1 = pp[1], p2 = pp[2], p3 = pp[3];
        #pragma unroll
        for (int u = 0; u < 8; u++) {
            fma2(acc[u][0], va[u], p0);
            fma2(acc[u][1], va[u], p1);
            fma2(acc[u][2], va[u], p2);
            fma2(acc[u][3], va[u], p3);
        }
    }
    #pragma unroll
    for (int u = 0; u < 8; u++) {
        int d = ty * 8 + u;
        float2 a0 = up2(acc[u][0]), a1 = up2(acc[u][1]);
        float2 a2 = up2(acc[u][2]), a3 = up2(acc[u][3]);
        float4 o0 = make_float4(a0.x, a0.y, a1.x, a1.y);
        float4 o1 = make_float4(a2.x, a2.y, a3.x, a3.y);
        *(float4*)(outp + (size_t)d * HWN + tx * 8)     = o0;
        *(float4*)(outp + (size_t)d * HWN + tx * 8 + 4) = o1;
    }
}

// Kernel 6: row attention. block (i,h,b), 64 threads.
__global__ __launch_bounds__(64) void attn_row_kernel()
{
    int i = blockIdx.x, h = blockIdx.y, b = blockIdx.z;
    size_t vbase = ((size_t)(b * DQKV + h * DHH)) * HWN + i * WW;
    size_t pbase = (((size_t)((b * NHH + h) * HH + i)) * WW) * PLEN;
    attn_core(g_V + vbase, g_P + pbase, PLEN, g_A + vbase);
}

// Kernel 7: column attention. block (j,h,b), 64 threads. writes g_AT.
__global__ __launch_bounds__(64) void attn_col_kernel()
{
    int j = blockIdx.x, h = blockIdx.y, b = blockIdx.z;
    size_t vbase = ((size_t)(b * DQKV + h * DHH)) * HWN + j * HH;
    size_t pcol  = ((size_t)((b * NHH + h) * HH) * WW + j) * PLEN + 64;
    attn_core(g_VT + vbase, g_P + pcol, (size_t)WW * PLEN, g_AT + vbase);
}

// =====================================================================
// Kernel 8: A[i][j] += AT[j][i] per (b,ch) image.
// =====================================================================
__global__ __launch_bounds__(256) void transpose_add_kernel()
{
    size_t base = (size_t)blockIdx.x * HWN;
    __shared__ float sm[64][65];
    int t = threadIdx.x;
    #pragma unroll
    for (int r = 0; r < 16; r++) {
        int idx = r * 256 + t;
        sm[idx >> 6][idx & 63] = g_AT[base + idx];
    }
    __syncthreads();
    #pragma unroll
    for (int r = 0; r < 16; r++) {
        int idx = r * 256 + t;
        g_A[base + idx] += sm[idx & 63][idx >> 6];
    }
}

// =====================================================================
// Kernel 9: output projection + residual — double-buffered (f32x2).
// =====================================================================
__global__ __launch_bounds__(256, 2) void proj_gemm(
    const float* __restrict__ x, const float* __restrict__ Wo,
    const float* __restrict__ bo, float* __restrict__ out)
{
    int mBlk = blockIdx.y * 128;
    int nBlk = blockIdx.x * 128;
    int b    = blockIdx.z;

    __shared__ float As[2][8][132];
    __shared__ float Bs[2][8][128];

    int t  = threadIdx.x;
    int tx = t & 15, ty = t >> 4;
    const float* Ab = g_A + (size_t)b * (DQKV * HWN);

    int aM[4], aK[4];
    #pragma unroll
    for (int r = 0; r < 4; r++) { int idx = r * 256 + t; aM[r] = idx >> 3; aK[r] = idx & 7; }
    int bK = t >> 5;
    int bN = (t & 31) * 4;

    u64 acc[8][4];
    #pragma unroll
    for (int i = 0; i < 8; i++)
        #pragma unroll
        for (int j = 0; j < 4; j++) acc[i][j] = 0ull;

    float aPf[4]; float4 bPf;
    #pragma unroll
    for (int r = 0; r < 4; r++)
        aPf[r] = Wo[(size_t)(mBlk + aM[r]) * DQKV + aK[r]];
    bPf = *(const float4*)(Ab + (size_t)bK * HWN + nBlk + bN);
    #pragma unroll
    for (int r = 0; r < 4; r++) As[0][aK[r]][aM[r]] = aPf[r];
    *(float4*)&Bs[0][bK][bN] = bPf;
    __syncthreads();

    int buf = 0;
    for (int k0 = 0; k0 < DQKV; k0 += 8) {
        int k0n = k0 + 8;
        bool more = (k0n < DQKV);
        if (more) {
            #pragma unroll
            for (int r = 0; r < 4; r++)
                aPf[r] = Wo[(size_t)(mBlk + aM[r]) * DQKV + k0n + aK[r]];
            bPf = *(const float4*)(Ab + (size_t)(k0n + bK) * HWN + nBlk + bN);
        }
        #pragma unroll
        for (int kk = 0; kk < 8; kk++) {
            float4 a0 = *(float4*)&As[buf][kk][ty * 8];
            float4 a1 = *(float4*)&As[buf][kk][ty * 8 + 4];
            u64 ap[8] = {pk2(a0.x), pk2(a0.y), pk2(a0.z), pk2(a0.w),
                         pk2(a1.x), pk2(a1.y), pk2(a1.z), pk2(a1.w)};
            const u64* bp = (const u64*)&Bs[buf][kk][tx * 8];
            u64 b0 = bp[0], b1 = bp[1], b2 = bp[2], b3 = bp[3];
            #pragma unroll
            for (int i = 0; i < 8; i++) {
                fma2(acc[i][0], ap[i], b0);
                fma2(acc[i][1], ap[i], b1);
                fma2(acc[i][2], ap[i], b2);
                fma2(acc[i][3], ap[i], b3);
            }
        }
        if (more) {
            #pragma unroll
            for (int r = 0; r < 4; r++) As[buf ^ 1][aK[r]][aM[r]] = aPf[r];
            *(float4*)&Bs[buf ^ 1][bK][bN] = bPf;
            __syncthreads();
            buf ^= 1;
        }
    }

    #pragma unroll
    for (int i = 0; i < 8; i++) {
        int m = mBlk + ty * 8 + i;
        float bi = bo[m];
        size_t oidx = ((size_t)(b * CC + m)) * HWN + nBlk + tx * 8;
        float4 x0 = *(const float4*)(x + oidx);
        float4 x1 = *(const float4*)(x + oidx + 4);
        float2 p0 = up2(acc[i][0]), p1 = up2(acc[i][1]);
        float2 p2 = up2(acc[i][2]), p3 = up2(acc[i][3]);
        float4 o0 = make_float4(p0.x + bi + x0.x, p0.y + bi + x0.y,
                                p1.x + bi + x0.z, p1.y + bi + x0.w);
        float4 o1 = make_float4(p2.x + bi + x1.x, p2.y + bi + x1.y,
                                p3.x + bi + x1.z, p3.y + bi + x1.w);
        *(float4*)(out + oidx)     = o0;
        *(float4*)(out + oidx + 4) = o1;
    }
}

// =====================================================================
extern "C" void kernel_launch(void* const* d_in, const int* in_sizes, int n_in,
                              void* d_out, int out_size)
{
    const float* x   = (const float*)d_in[0];
    const float* pos = (const float*)d_in[1];
    const float* Wk  = (const float*)d_in[2];
    const float* bk  = (const float*)d_in[3];
    const float* Wq  = (const float*)d_in[4];
    const float* bq  = (const float*)d_in[5];
    const float* Wv  = (const float*)d_in[6];
    const float* bv  = (const float*)d_in[7];
    const float* Wo  = (const float*)d_in[8];
    const float* bo  = (const float*)d_in[9];
    float* out = (float*)d_out;

    qkv_gemm<<<dim3(32, 12, BB), 256>>>(x, pos, Wq, bq, Wk, bk, Wv, bv);
    transpose3_kernel<<<dim3(BB * DQKV, 3), 256>>>();
    logits_row_kernel<<<dim3(HH, NHH, BB), 64>>>();
    logits_col_kernel<<<dim3(WW, NHH, BB), 64>>>();
    softmax_kernel<<<65536, 256>>>();
    attn_row_kernel<<<dim3(HH, NHH, BB), 64>>>();
    attn_col_kernel<<<dim3(WW, NHH, BB), 64>>>();
    transpose_add_kernel<<<BB * DQKV, 256>>>();
    proj_gemm<<<dim3(32, 2, BB), 256>>>(x, Wo, bo, out);
}

// round 10
// speedup vs baseline: 1.5846x; 1.4897x over previous
#include <cuda_runtime.h>
#include <cstdint>

// ---------------- problem constants ----------------
#define BB   16
#define CC   256
#define HH   64
#define WW   64
#define NHH  8
#define DHH  64
#define CIN  260
#define KPAD 264                 // CIN padded for XT
#define DQKV 512
#define HWN  4096               // H*W
#define PLEN 128                // W+H logits per query
#define SCALE 0.08838834764831843f  // 1/sqrt(128)

typedef unsigned long long u64;

// ---------------- f32x2 packed-FMA helpers ----------------
__device__ __forceinline__ u64 pk2(float x) {
    u64 r; asm("mov.b64 %0, {%1, %1};" : "=l"(r) : "f"(x)); return r;
}
__device__ __forceinline__ void fma2(u64 &d, u64 a, u64 b) {
    asm("fma.rn.f32x2 %0, %1, %2, %3;" : "=l"(d) : "l"(a), "l"(b), "l"(d));
}
__device__ __forceinline__ float2 up2(u64 v) {
    float lo, hi; asm("mov.b64 {%0, %1}, %2;" : "=f"(lo), "=f"(hi) : "l"(v));
    return make_float2(lo, hi);
}

// ---------------- tf32 helpers (plain sm_80+ PTX, safe on compute_103) ----
__device__ __forceinline__ uint32_t f2tf32(float f) {
    uint32_t u;
    asm("cvt.rna.tf32.f32 %0, %1;" : "=r"(u) : "f"(f));
    return u;
}
__device__ __forceinline__ void mma_tf32(float c[4], const uint32_t a[4],
                                         const uint32_t bfr[2]) {
    asm volatile(
        "mma.sync.aligned.m16n8k8.row.col.f32.tf32.tf32.f32 "
        "{%0,%1,%2,%3}, {%4,%5,%6,%7}, {%8,%9}, {%0,%1,%2,%3};"
        : "+f"(c[0]), "+f"(c[1]), "+f"(c[2]), "+f"(c[3])
        : "r"(a[0]), "r"(a[1]), "r"(a[2]), "r"(a[3]),
          "r"(bfr[0]), "r"(bfr[1]));
}

// ---------------- device scratch ----------------
#define TSZ ((size_t)BB * DQKV * HWN)
__device__ float g_Q [TSZ];
__device__ float g_K [TSZ];
__device__ float g_V [TSZ];
__device__ float g_QT[TSZ];
__device__ float g_KT[TSZ];
__device__ float g_VT[TSZ];
__device__ float g_A [TSZ];
__device__ float g_AT[TSZ];
__device__ float g_P [(size_t)BB * NHH * HH * WW * PLEN];
__device__ float g_XT[(size_t)BB * HWN * KPAD];   // xp transposed [b][p][c]

// =====================================================================
// Kernel 0: transpose xp = concat(x,pos) -> g_XT [b][p][264]
// =====================================================================
__global__ __launch_bounds__(256) void xpose_x(
    const float* __restrict__ x, const float* __restrict__ pos)
{
    __shared__ float tile[64][65];
    int t = threadIdx.x;
    int p0 = blockIdx.x * 64, c0 = blockIdx.y * 64, b = blockIdx.z;
    #pragma unroll
    for (int r = 0; r < 16; r++) {
        int idx = r * 256 + t;
        int cc = idx >> 6, pp = idx & 63;
        int c = c0 + cc;
        float v = 0.0f;
        if (c < CC)       v = x[((size_t)b * CC + c) * HWN + p0 + pp];
        else if (c < CIN) v = pos[(size_t)(c - CC) * HWN + p0 + pp];
        tile[cc][pp] = v;
    }
    __syncthreads();
    #pragma unroll
    for (int r = 0; r < 16; r++) {
        int idx = r * 256 + t;
        int pp = idx >> 6, cc = idx & 63;
        int c = c0 + cc;
        if (c < KPAD)
            g_XT[((size_t)b * HWN + p0 + pp) * KPAD + c] = tile[cc][pp];
    }
}

// =====================================================================
// Kernel 1: QKV projection via mma.sync tf32 (m16n8k8).
// grid (32 pT, 12 nT, 16 b), 256 threads.
// Block: 128 ch x 128 p. A = W[ch][k] (k-major), B = XT[p][k] (k-major).
// K chunks of 32 in smem (tf32-converted at fill, pad 36).
// 8 warps 2(M)x4(N); warp tile 64x32 = 4x4 mma frags.
// =====================================================================
__global__ __launch_bounds__(256, 2) void qkv_mma(
    const float* __restrict__ Wq, const float* __restrict__ bq,
    const float* __restrict__ Wk, const float* __restrict__ bk,
    const float* __restrict__ Wv, const float* __restrict__ bv)
{
    int pT = blockIdx.x, nT = blockIdx.y, b = blockIdx.z;
    int which = nT >> 2;
    int mOff  = (nT & 3) * 128;
    const float* Wt   = (which == 0) ? Wq : (which == 1) ? Wk : Wv;
    const float* bias = (which == 0) ? bq : (which == 1) ? bk : bv;
    float*       outp = (which == 0) ? g_Q : (which == 1) ? g_K : g_V;

    __shared__ uint32_t As[128][36];   // W rows (tf32 bits)
    __shared__ uint32_t Bs[128][36];   // XT rows (tf32 bits)

    int t = threadIdx.x, lane = t & 31, wid = t >> 5;
    int g = lane >> 2, tig = lane & 3;
    int wm = (wid >> 2) * 64, wn = (wid & 3) * 32;

    const float* xt = g_XT + ((size_t)b * HWN + (size_t)pT * 128) * KPAD;

    float c[4][4][4];
    #pragma unroll
    for (int mi = 0; mi < 4; mi++)
        #pragma unroll
        for (int ni = 0; ni < 4; ni++)
            #pragma unroll
            for (int e = 0; e < 4; e++) c[mi][ni][e] = 0.0f;

    for (int c0 = 0; c0 < 9; c0++) {
        int kBase = c0 * 32;
        // fill As (W) and Bs (XT): 1024 float4 each, 4 per thread
        #pragma unroll
        for (int r = 0; r < 4; r++) {
            int idx = r * 256 + t;
            int row = idx >> 3, q = idx & 7;
            int k4 = kBase + q * 4;
            float4 va = make_float4(0.f, 0.f, 0.f, 0.f);
            if (k4 <= CIN - 4)
                va = *(const float4*)(Wt + (size_t)(mOff + row) * CIN + k4);
            As[row][q * 4 + 0] = f2tf32(va.x);
            As[row][q * 4 + 1] = f2tf32(va.y);
            As[row][q * 4 + 2] = f2tf32(va.z);
            As[row][q * 4 + 3] = f2tf32(va.w);
            float4 vb = make_float4(0.f, 0.f, 0.f, 0.f);
            if (k4 <= KPAD - 4)
                vb = *(const float4*)(xt + (size_t)row * KPAD + k4);
            Bs[row][q * 4 + 0] = f2tf32(vb.x);
            Bs[row][q * 4 + 1] = f2tf32(vb.y);
            Bs[row][q * 4 + 2] = f2tf32(vb.z);
            Bs[row][q * 4 + 3] = f2tf32(vb.w);
        }
        __syncthreads();
        #pragma unroll
        for (int ks = 0; ks < 4; ks++) {
            int kk = ks * 8;
            uint32_t a[4][4], bfr[4][2];
            #pragma unroll
            for (int mi = 0; mi < 4; mi++) {
                int row = wm + mi * 16 + g;
                a[mi][0] = As[row][kk + tig];
                a[mi][1] = As[row + 8][kk + tig];
                a[mi][2] = As[row][kk + tig + 4];
                a[mi][3] = As[row + 8][kk + tig + 4];
            }
            #pragma unroll
            for (int ni = 0; ni < 4; ni++) {
                int col = wn + ni * 8 + g;
                bfr[ni][0] = Bs[col][kk + tig];
                bfr[ni][1] = Bs[col][kk + tig + 4];
            }
            #pragma unroll
            for (int mi = 0; mi < 4; mi++)
                #pragma unroll
                for (int ni = 0; ni < 4; ni++)
                    mma_tf32(c[mi][ni], a[mi], bfr[ni]);
        }
        __syncthreads();
    }

    // epilogue: c frag (row=g/+8, col=2*tig/+1) -> out[b][ch][p] + bias
    #pragma unroll
    for (int mi = 0; mi < 4; mi++) {
        int row0 = wm + mi * 16 + g;
        float bi0 = bias[mOff + row0];
        float bi1 = bias[mOff + row0 + 8];
        float* o0 = outp + ((size_t)b * DQKV + mOff + row0) * HWN + (size_t)pT * 128;
        float* o1 = o0 + (size_t)8 * HWN;
        #pragma unroll
        for (int ni = 0; ni < 4; ni++) {
            int col = wn + ni * 8 + tig * 2;
            float2 v0 = make_float2(c[mi][ni][0] + bi0, c[mi][ni][1] + bi0);
            float2 v1 = make_float2(c[mi][ni][2] + bi1, c[mi][ni][3] + bi1);
            *(float2*)(o0 + col) = v0;
            *(float2*)(o1 + col) = v1;
        }
    }
}

// =====================================================================
// Kernel 2: transpose each 64x64 image of Q,K,V -> QT,KT,VT
// =====================================================================
__global__ __launch_bounds__(256) void transpose3_kernel()
{
    const float* src = (blockIdx.y == 0) ? g_Q : (blockIdx.y == 1) ? g_K : g_V;
    float*       dst = (blockIdx.y == 0) ? g_QT : (blockIdx.y == 1) ? g_KT : g_VT;
    size_t base = (size_t)blockIdx.x * HWN;
    __shared__ float sm[64][65];
    int t = threadIdx.x;
    #pragma unroll
    for (int r = 0; r < 16; r++) {
        int idx = r * 256 + t;
        sm[idx >> 6][idx & 63] = src[base + idx];
    }
    __syncthreads();
    #pragma unroll
    for (int r = 0; r < 16; r++) {
        int idx = r * 256 + t;
        dst[base + idx] = sm[idx & 63][idx >> 6];
    }
}

// =====================================================================
// Kernel 3: row logits (f32x2, 256 thr). block (i, h, b).
// =====================================================================
__global__ __launch_bounds__(256) void logits_row_kernel()
{
    int i = blockIdx.x, h = blockIdx.y, b = blockIdx.z;
    __shared__ float qs[64][64];
    __shared__ float ks[64][64];
    size_t base = ((size_t)(b * DQKV + h * DHH)) * HWN + i * WW;
    int t = threadIdx.x;
    #pragma unroll
    for (int r = 0; r < 16; r++) {
        int idx = r * 256 + t;
        int d = idx >> 6, j = idx & 63;
        qs[d][j] = g_Q[base + (size_t)d * HWN + j];
        ks[d][j] = g_K[base + (size_t)d * HWN + j];
    }
    __syncthreads();
    int tx = t & 15, ty = t >> 4;
    u64 acc[4][2];
    #pragma unroll
    for (int u = 0; u < 4; u++) { acc[u][0] = 0ull; acc[u][1] = 0ull; }
    #pragma unroll
    for (int d = 0; d < 64; d++) {
        float4 q4 = *(float4*)&qs[d][ty * 4];
        const u64* kp = (const u64*)&ks[d][tx * 4];
        u64 k0 = kp[0], k1 = kp[1];
        u64 qa[4] = {pk2(q4.x), pk2(q4.y), pk2(q4.z), pk2(q4.w)};
        #pragma unroll
        for (int u = 0; u < 4; u++) {
            fma2(acc[u][0], qa[u], k0);
            fma2(acc[u][1], qa[u], k1);
        }
    }
    size_t pbase = (((size_t)((b * NHH + h) * HH + i)) * WW) * PLEN;
    #pragma unroll
    for (int u = 0; u < 4; u++) {
        int j = ty * 4 + u;
        float2 p0 = up2(acc[u][0]), p1 = up2(acc[u][1]);
        float4 o = make_float4(p0.x * SCALE, p0.y * SCALE, p1.x * SCALE, p1.y * SCALE);
        *(float4*)&g_P[pbase + (size_t)j * PLEN + tx * 4] = o;
    }
}

// =====================================================================
// Kernel 4: column logits (f32x2, 256 thr). block (j, h, b).
// =====================================================================
__global__ __launch_bounds__(256) void logits_col_kernel()
{
    int j = blockIdx.x, h = blockIdx.y, b = blockIdx.z;
    __shared__ float qs[64][64];
    __shared__ float ks[64][64];
    size_t base = ((size_t)(b * DQKV + h * DHH)) * HWN + j * HH;
    int t = threadIdx.x;
    #pragma unroll
    for (int r = 0; r < 16; r++) {
        int idx = r * 256 + t;
        int d = idx >> 6, ii = idx & 63;
        qs[d][ii] = g_QT[base + (size_t)d * HWN + ii];
        ks[d][ii] = g_KT[base + (size_t)d * HWN + ii];
    }
    __syncthreads();
    int tx = t & 15, ty = t >> 4;
    u64 acc[4][2];
    #pragma unroll
    for (int u = 0; u < 4; u++) { acc[u][0] = 0ull; acc[u][1] = 0ull; }
    #pragma unroll
    for (int d = 0; d < 64; d++) {
        float4 q4 = *(float4*)&qs[d][ty * 4];
        const u64* kp = (const u64*)&ks[d][tx * 4];
        u64 k0 = kp[0], k1 = kp[1];
        u64 qa[4] = {pk2(q4.x), pk2(q4.y), pk2(q4.z), pk2(q4.w)};
        #pragma unroll
        for (int u = 0; u < 4; u++) {
            fma2(acc[u][0], qa[u], k0);
            fma2(acc[u][1], qa[u], k1);
        }
    }
    size_t pre = ((size_t)((b * NHH + h) * HH) * WW + j) * PLEN + 64;
    #pragma unroll
    for (int u = 0; u < 4; u++) {
        int i = ty * 4 + u;
        float2 p0 = up2(acc[u][0]), p1 = up2(acc[u][1]);
        float4 o = make_float4(p0.x * SCALE, p0.y * SCALE, p1.x * SCALE, p1.y * SCALE);
        *(float4*)&g_P[pre + (size_t)i * (WW * PLEN) + tx * 4] = o;
    }
}

// =====================================================================
// Kernel 5: softmax over 128 logits per query, in place.
// =====================================================================
__global__ __launch_bounds__(256) void softmax_kernel()
{
    size_t row = (size_t)blockIdx.x * 8 + (threadIdx.x >> 5);
    int lane = threadIdx.x & 31;
    float* p = g_P + row * PLEN + lane * 4;
    float4 v = *(float4*)p;
    float m = fmaxf(fmaxf(v.x, v.y), fmaxf(v.z, v.w));
    #pragma unroll
    for (int o = 16; o; o >>= 1) m = fmaxf(m, __shfl_xor_sync(0xffffffffu, m, o));
    v.x = __expf(v.x - m); v.y = __expf(v.y - m);
    v.z = __expf(v.z - m); v.w = __expf(v.w - m);
    float s = v.x + v.y + v.z + v.w;
    #pragma unroll
    for (int o = 16; o; o >>= 1) s += __shfl_xor_sync(0xffffffffu, s, o);
    float inv = 1.0f / s;
    v.x *= inv; v.y *= inv; v.z *= inv; v.w *= inv;
    *(float4*)p = v;
}

// =====================================================================
// Kernel 6: row attention (f32x2, 256 thr). block (i,h,b).
// =====================================================================
__global__ __launch_bounds__(256) void attn_row_kernel()
{
    int i = blockIdx.x, h = blockIdx.y, b = blockIdx.z;
    __shared__ float vsT[64][68];
    __shared__ float psT[64][68];
    size_t vbase = ((size_t)(b * DQKV + h * DHH)) * HWN + i * WW;
    size_t pbase = (((size_t)((b * NHH + h) * HH + i)) * WW) * PLEN;
    int t = threadIdx.x;
    #pragma unroll
    for (int r = 0; r < 16; r++) {
        int idx = r * 256 + t;
        int a = idx >> 6, k = idx & 63;
        vsT[k][a] = g_V[vbase + (size_t)a * HWN + k];
        psT[k][a] = g_P[pbase + (size_t)a * PLEN + k];
    }
    __syncthreads();
    int tx = t & 15, ty = t >> 4;
    u64 acc[4][2];
    #pragma unroll
    for (int u = 0; u < 4; u++) { acc[u][0] = 0ull; acc[u][1] = 0ull; }
    #pragma unroll
    for (int k = 0; k < 64; k++) {
        float4 v4 = *(float4*)&vsT[k][ty * 4];
        const u64* pp = (const u64*)&psT[k][tx * 4];
        u64 p0 = pp[0], p1 = pp[1];
        u64 va[4] = {pk2(v4.x), pk2(v4.y), pk2(v4.z), pk2(v4.w)};
        #pragma unroll
        for (int u = 0; u < 4; u++) {
            fma2(acc[u][0], va[u], p0);
            fma2(acc[u][1], va[u], p1);
        }
    }
    #pragma unroll
    for (int u = 0; u < 4; u++) {
        int d = ty * 4 + u;
        float2 a0 = up2(acc[u][0]), a1 = up2(acc[u][1]);
        float4 o = make_float4(a0.x, a0.y, a1.x, a1.y);
        *(float4*)&g_A[vbase + (size_t)d * HWN + tx * 4] = o;
    }
}

// =====================================================================
// Kernel 7: column attention (f32x2, 256 thr). writes g_AT.
// =====================================================================
__global__ __launch_bounds__(256) void attn_col_kernel()
{
    int j = blockIdx.x, h = blockIdx.y, b = blockIdx.z;
    __shared__ float vsT[64][68];
    __shared__ float psT[64][68];
    size_t vbase = ((size_t)(b * DQKV + h * DHH)) * HWN + j * HH;
    size_t pcol  = ((size_t)((b * NHH + h) * HH) * WW + j) * PLEN + 64;
    int t = threadIdx.x;
    #pragma unroll
    for (int r = 0; r < 16; r++) {
        int idx = r * 256 + t;
        int a = idx >> 6, k = idx & 63;
        vsT[k][a] = g_VT[vbase + (size_t)a * HWN + k];
        psT[k][a] = g_P[pcol + (size_t)a * (WW * PLEN) + k];
    }
    __syncthreads();
    int tx = t & 15, ty = t >> 4;
    u64 acc[4][2];
    #pragma unroll
    for (int u = 0; u < 4; u++) { acc[u][0] = 0ull; acc[u][1] = 0ull; }
    #pragma unroll
    for (int k = 0; k < 64; k++) {
        float4 v4 = *(float4*)&vsT[k][ty * 4];
        const u64* pp = (const u64*)&psT[k][tx * 4];
        u64 p0 = pp[0], p1 = pp[1];
        u64 va[4] = {pk2(v4.x), pk2(v4.y), pk2(v4.z), pk2(v4.w)};
        #pragma unroll
        for (int u = 0; u < 4; u++) {
            fma2(acc[u][0], va[u], p0);
            fma2(acc[u][1], va[u], p1);
        }
    }
    #pragma unroll
    for (int u = 0; u < 4; u++) {
        int d = ty * 4 + u;
        float2 a0 = up2(acc[u][0]), a1 = up2(acc[u][1]);
        float4 o = make_float4(a0.x, a0.y, a1.x, a1.y);
        *(float4*)&g_AT[vbase + (size_t)d * HWN + tx * 4] = o;
    }
}

// =====================================================================
// Kernel 8: A[i][j] += AT[j][i] per (b,ch) image.
// =====================================================================
__global__ __launch_bounds__(256) void transpose_add_kernel()
{
    size_t base = (size_t)blockIdx.x * HWN;
    __shared__ float sm[64][65];
    int t = threadIdx.x;
    #pragma unroll
    for (int r = 0; r < 16; r++) {
        int idx = r * 256 + t;
        sm[idx >> 6][idx & 63] = g_AT[base + idx];
    }
    __syncthreads();
    #pragma unroll
    for (int r = 0; r < 16; r++) {
        int idx = r * 256 + t;
        g_A[base + idx] += sm[idx & 63][idx >> 6];
    }
}

// =====================================================================
// Kernel 9: output projection + residual — double-buffered (f32x2).
// =====================================================================
__global__ __launch_bounds__(256, 2) void proj_gemm(
    const float* __restrict__ x, const float* __restrict__ Wo,
    const float* __restrict__ bo, float* __restrict__ out)
{
    int mBlk = blockIdx.y * 128;
    int nBlk = blockIdx.x * 128;
    int b    = blockIdx.z;

    __shared__ float As[2][8][132];
    __shared__ float Bs[2][8][128];

    int t  = threadIdx.x;
    int tx = t & 15, ty = t >> 4;
    const float* Ab = g_A + (size_t)b * (DQKV * HWN);

    int aM[4], aK[4];
    #pragma unroll
    for (int r = 0; r < 4; r++) { int idx = r * 256 + t; aM[r] = idx >> 3; aK[r] = idx & 7; }
    int bK = t >> 5;
    int bN = (t & 31) * 4;

    u64 acc[8][4];
    #pragma unroll
    for (int i = 0; i < 8; i++)
        #pragma unroll
        for (int j = 0; j < 4; j++) acc[i][j] = 0ull;

    float aPf[4]; float4 bPf;
    #pragma unroll
    for (int r = 0; r < 4; r++)
        aPf[r] = Wo[(size_t)(mBlk + aM[r]) * DQKV + aK[r]];
    bPf = *(const float4*)(Ab + (size_t)bK * HWN + nBlk + bN);
    #pragma unroll
    for (int r = 0; r < 4; r++) As[0][aK[r]][aM[r]] = aPf[r];
    *(float4*)&Bs[0][bK][bN] = bPf;
    __syncthreads();

    int buf = 0;
    for (int k0 = 0; k0 < DQKV; k0 += 8) {
        int k0n = k0 + 8;
        bool more = (k0n < DQKV);
        if (more) {
            #pragma unroll
            for (int r = 0; r < 4; r++)
                aPf[r] = Wo[(size_t)(mBlk + aM[r]) * DQKV + k0n + aK[r]];
            bPf = *(const float4*)(Ab + (size_t)(k0n + bK) * HWN + nBlk + bN);
        }
        #pragma unroll
        for (int kk = 0; kk < 8; kk++) {
            float4 a0 = *(float4*)&As[buf][kk][ty * 8];
            float4 a1 = *(float4*)&As[buf][kk][ty * 8 + 4];
            u64 ap[8] = {pk2(a0.x), pk2(a0.y), pk2(a0.z), pk2(a0.w),
                         pk2(a1.x), pk2(a1.y), pk2(a1.z), pk2(a1.w)};
            const u64* bp = (const u64*)&Bs[buf][kk][tx * 8];
            u64 b0 = bp[0], b1 = bp[1], b2 = bp[2], b3 = bp[3];
            #pragma unroll
            for (int i = 0; i < 8; i++) {
                fma2(acc[i][0], ap[i], b0);
                fma2(acc[i][1], ap[i], b1);
                fma2(acc[i][2], ap[i], b2);
                fma2(acc[i][3], ap[i], b3);
            }
        }
        if (more) {
            #pragma unroll
            for (int r = 0; r < 4; r++) As[buf ^ 1][aK[r]][aM[r]] = aPf[r];
            *(float4*)&Bs[buf ^ 1][bK][bN] = bPf;
            __syncthreads();
            buf ^= 1;
        }
    }

    #pragma unroll
    for (int i = 0; i < 8; i++) {
        int m = mBlk + ty * 8 + i;
        float bi = bo[m];
        size_t oidx = ((size_t)(b * CC + m)) * HWN + nBlk + tx * 8;
        float4 x0 = *(const float4*)(x + oidx);
        float4 x1 = *(const float4*)(x + oidx + 4);
        float2 p0 = up2(acc[i][0]), p1 = up2(acc[i][1]);
        float2 p2 = up2(acc[i][2]), p3 = up2(acc[i][3]);
        float4 o0 = make_float4(p0.x + bi + x0.x, p0.y + bi + x0.y,
                                p1.x + bi + x0.z, p1.y + bi + x0.w);
        float4 o1 = make_float4(p2.x + bi + x1.x, p2.y + bi + x1.y,
                                p3.x + bi + x1.z, p3.y + bi + x1.w);
        *(float4*)(out + oidx)     = o0;
        *(float4*)(out + oidx + 4) = o1;
    }
}

// =====================================================================
extern "C" void kernel_launch(void* const* d_in, const int* in_sizes, int n_in,
                              void* d_out, int out_size)
{
    const float* x   = (const float*)d_in[0];
    const float* pos = (const float*)d_in[1];
    const float* Wk  = (const float*)d_in[2];
    const float* bk  = (const float*)d_in[3];
    const float* Wq  = (const float*)d_in[4];
    const float* bq  = (const float*)d_in[5];
    const float* Wv  = (const float*)d_in[6];
    const float* bv  = (const float*)d_in[7];
    const float* Wo  = (const float*)d_in[8];
    const float* bo  = (const float*)d_in[9];
    float* out = (float*)d_out;

    xpose_x<<<dim3(64, 5, BB), 256>>>(x, pos);
    qkv_mma<<<dim3(32, 12, BB), 256>>>(Wq, bq, Wk, bk, Wv, bv);
    transpose3_kernel<<<dim3(BB * DQKV, 3), 256>>>();
    logits_row_kernel<<<dim3(HH, NHH, BB), 256>>>();
    logits_col_kernel<<<dim3(WW, NHH, BB), 256>>>();
    softmax_kernel<<<65536, 256>>>();
    attn_row_kernel<<<dim3(HH, NHH, BB), 256>>>();
    attn_col_kernel<<<dim3(WW, NHH, BB), 256>>>();
    transpose_add_kernel<<<BB * DQKV, 256>>>();
    proj_gemm<<<dim3(32, 2, BB), 256>>>(x, Wo, bo, out);
}

// round 11
// speedup vs baseline: 1.7700x; 1.1170x over previous
#include <cuda_runtime.h>
#include <cstdint>

// ---------------- problem constants ----------------
#define BB   16
#define CC   256
#define HH   64
#define WW   64
#define NHH  8
#define DHH  64
#define CIN  260
#define KPAD 264                 // CIN padded for XT
#define DQKV 512
#define HWN  4096               // H*W
#define PLEN 128                // W+H logits per query
#define SCALE 0.08838834764831843f  // 1/sqrt(128)

typedef unsigned long long u64;

// ---------------- f32x2 packed-FMA helpers ----------------
__device__ __forceinline__ u64 pk2(float x) {
    u64 r; asm("mov.b64 %0, {%1, %1};" : "=l"(r) : "f"(x)); return r;
}
__device__ __forceinline__ void fma2(u64 &d, u64 a, u64 b) {
    asm("fma.rn.f32x2 %0, %1, %2, %3;" : "=l"(d) : "l"(a), "l"(b), "l"(d));
}
__device__ __forceinline__ float2 up2(u64 v) {
    float lo, hi; asm("mov.b64 {%0, %1}, %2;" : "=f"(lo), "=f"(hi) : "l"(v));
    return make_float2(lo, hi);
}

// ---------------- tf32 helpers (plain sm_80+ PTX) ----------------
__device__ __forceinline__ uint32_t f2tf32(float f) {
    uint32_t u;
    asm("cvt.rna.tf32.f32 %0, %1;" : "=r"(u) : "f"(f));
    return u;
}
__device__ __forceinline__ void mma_tf32(float c[4], const uint32_t a[4],
                                         const uint32_t bfr[2]) {
    asm volatile(
        "mma.sync.aligned.m16n8k8.row.col.f32.tf32.tf32.f32 "
        "{%0,%1,%2,%3}, {%4,%5,%6,%7}, {%8,%9}, {%0,%1,%2,%3};"
        : "+f"(c[0]), "+f"(c[1]), "+f"(c[2]), "+f"(c[3])
        : "r"(a[0]), "r"(a[1]), "r"(a[2]), "r"(a[3]),
          "r"(bfr[0]), "r"(bfr[1]));
}

// ---------------- device scratch ----------------
#define TSZ ((size_t)BB * DQKV * HWN)
__device__ float g_Q [TSZ];
__device__ float g_K [TSZ];
__device__ float g_V [TSZ];
__device__ float g_QT[TSZ];
__device__ float g_KT[TSZ];
__device__ float g_VT[TSZ];
__device__ float g_A [TSZ];    // a_w in [b][p][ch] layout
__device__ float g_AT[TSZ];    // a_h in [b][p][ch] layout
__device__ float g_P [(size_t)BB * NHH * HH * WW * PLEN];
__device__ float g_XT[(size_t)BB * HWN * KPAD];   // xp transposed [b][p][c]

// =====================================================================
// Kernel 0: transpose xp = concat(x,pos) -> g_XT [b][p][264]
// =====================================================================
__global__ __launch_bounds__(256) void xpose_x(
    const float* __restrict__ x, const float* __restrict__ pos)
{
    __shared__ float tile[64][65];
    int t = threadIdx.x;
    int p0 = blockIdx.x * 64, c0 = blockIdx.y * 64, b = blockIdx.z;
    #pragma unroll
    for (int r = 0; r < 16; r++) {
        int idx = r * 256 + t;
        int cc = idx >> 6, pp = idx & 63;
        int c = c0 + cc;
        float v = 0.0f;
        if (c < CC)       v = x[((size_t)b * CC + c) * HWN + p0 + pp];
        else if (c < CIN) v = pos[(size_t)(c - CC) * HWN + p0 + pp];
        tile[cc][pp] = v;
    }
    __syncthreads();
    #pragma unroll
    for (int r = 0; r < 16; r++) {
        int idx = r * 256 + t;
        int pp = idx >> 6, cc = idx & 63;
        int c = c0 + cc;
        if (c < KPAD)
            g_XT[((size_t)b * HWN + p0 + pp) * KPAD + c] = tile[cc][pp];
    }
}

// =====================================================================
// Kernel 1: QKV projection via mma.sync tf32 (m16n8k8).
// =====================================================================
__global__ __launch_bounds__(256, 2) void qkv_mma(
    const float* __restrict__ Wq, const float* __restrict__ bq,
    const float* __restrict__ Wk, const float* __restrict__ bk,
    const float* __restrict__ Wv, const float* __restrict__ bv)
{
    int pT = blockIdx.x, nT = blockIdx.y, b = blockIdx.z;
    int which = nT >> 2;
    int mOff  = (nT & 3) * 128;
    const float* Wt   = (which == 0) ? Wq : (which == 1) ? Wk : Wv;
    const float* bias = (which == 0) ? bq : (which == 1) ? bk : bv;
    float*       outp = (which == 0) ? g_Q : (which == 1) ? g_K : g_V;

    __shared__ uint32_t As[128][36];
    __shared__ uint32_t Bs[128][36];

    int t = threadIdx.x, lane = t & 31, wid = t >> 5;
    int g = lane >> 2, tig = lane & 3;
    int wm = (wid >> 2) * 64, wn = (wid & 3) * 32;

    const float* xt = g_XT + ((size_t)b * HWN + (size_t)pT * 128) * KPAD;

    float c[4][4][4];
    #pragma unroll
    for (int mi = 0; mi < 4; mi++)
        #pragma unroll
        for (int ni = 0; ni < 4; ni++)
            #pragma unroll
            for (int e = 0; e < 4; e++) c[mi][ni][e] = 0.0f;

    for (int c0 = 0; c0 < 9; c0++) {
        int kBase = c0 * 32;
        #pragma unroll
        for (int r = 0; r < 4; r++) {
            int idx = r * 256 + t;
            int row = idx >> 3, q = idx & 7;
            int k4 = kBase + q * 4;
            float4 va = make_float4(0.f, 0.f, 0.f, 0.f);
            if (k4 <= CIN - 4)
                va = *(const float4*)(Wt + (size_t)(mOff + row) * CIN + k4);
            As[row][q * 4 + 0] = f2tf32(va.x);
            As[row][q * 4 + 1] = f2tf32(va.y);
            As[row][q * 4 + 2] = f2tf32(va.z);
            As[row][q * 4 + 3] = f2tf32(va.w);
            float4 vb = make_float4(0.f, 0.f, 0.f, 0.f);
            if (k4 <= KPAD - 4)
                vb = *(const float4*)(xt + (size_t)row * KPAD + k4);
            Bs[row][q * 4 + 0] = f2tf32(vb.x);
            Bs[row][q * 4 + 1] = f2tf32(vb.y);
            Bs[row][q * 4 + 2] = f2tf32(vb.z);
            Bs[row][q * 4 + 3] = f2tf32(vb.w);
        }
        __syncthreads();
        #pragma unroll
        for (int ks = 0; ks < 4; ks++) {
            int kk = ks * 8;
            uint32_t a[4][4], bfr[4][2];
            #pragma unroll
            for (int mi = 0; mi < 4; mi++) {
                int row = wm + mi * 16 + g;
                a[mi][0] = As[row][kk + tig];
                a[mi][1] = As[row + 8][kk + tig];
                a[mi][2] = As[row][kk + tig + 4];
                a[mi][3] = As[row + 8][kk + tig + 4];
            }
            #pragma unroll
            for (int ni = 0; ni < 4; ni++) {
                int col = wn + ni * 8 + g;
                bfr[ni][0] = Bs[col][kk + tig];
                bfr[ni][1] = Bs[col][kk + tig + 4];
            }
            #pragma unroll
            for (int mi = 0; mi < 4; mi++)
                #pragma unroll
                for (int ni = 0; ni < 4; ni++)
                    mma_tf32(c[mi][ni], a[mi], bfr[ni]);
        }
        __syncthreads();
    }

    #pragma unroll
    for (int mi = 0; mi < 4; mi++) {
        int row0 = wm + mi * 16 + g;
        float bi0 = bias[mOff + row0];
        float bi1 = bias[mOff + row0 + 8];
        float* o0 = outp + ((size_t)b * DQKV + mOff + row0) * HWN + (size_t)pT * 128;
        float* o1 = o0 + (size_t)8 * HWN;
        #pragma unroll
        for (int ni = 0; ni < 4; ni++) {
            int col = wn + ni * 8 + tig * 2;
            float2 v0 = make_float2(c[mi][ni][0] + bi0, c[mi][ni][1] + bi0);
            float2 v1 = make_float2(c[mi][ni][2] + bi1, c[mi][ni][3] + bi1);
            *(float2*)(o0 + col) = v0;
            *(float2*)(o1 + col) = v1;
        }
    }
}

// =====================================================================
// Kernel 2: transpose each 64x64 image of Q,K,V -> QT,KT,VT
// =====================================================================
__global__ __launch_bounds__(256) void transpose3_kernel()
{
    const float* src = (blockIdx.y == 0) ? g_Q : (blockIdx.y == 1) ? g_K : g_V;
    float*       dst = (blockIdx.y == 0) ? g_QT : (blockIdx.y == 1) ? g_KT : g_VT;
    size_t base = (size_t)blockIdx.x * HWN;
    __shared__ float sm[64][65];
    int t = threadIdx.x;
    #pragma unroll
    for (int r = 0; r < 16; r++) {
        int idx = r * 256 + t;
        sm[idx >> 6][idx & 63] = src[base + idx];
    }
    __syncthreads();
    #pragma unroll
    for (int r = 0; r < 16; r++) {
        int idx = r * 256 + t;
        dst[base + idx] = sm[idx & 63][idx >> 6];
    }
}

// =====================================================================
// Kernel 3: row logits (f32x2, 256 thr). block (i, h, b).
// =====================================================================
__global__ __launch_bounds__(256) void logits_row_kernel()
{
    int i = blockIdx.x, h = blockIdx.y, b = blockIdx.z;
    __shared__ float qs[64][64];
    __shared__ float ks[64][64];
    size_t base = ((size_t)(b * DQKV + h * DHH)) * HWN + i * WW;
    int t = threadIdx.x;
    #pragma unroll
    for (int r = 0; r < 16; r++) {
        int idx = r * 256 + t;
        int d = idx >> 6, j = idx & 63;
        qs[d][j] = g_Q[base + (size_t)d * HWN + j];
        ks[d][j] = g_K[base + (size_t)d * HWN + j];
    }
    __syncthreads();
    int tx = t & 15, ty = t >> 4;
    u64 acc[4][2];
    #pragma unroll
    for (int u = 0; u < 4; u++) { acc[u][0] = 0ull; acc[u][1] = 0ull; }
    #pragma unroll
    for (int d = 0; d < 64; d++) {
        float4 q4 = *(float4*)&qs[d][ty * 4];
        const u64* kp = (const u64*)&ks[d][tx * 4];
        u64 k0 = kp[0], k1 = kp[1];
        u64 qa[4] = {pk2(q4.x), pk2(q4.y), pk2(q4.z), pk2(q4.w)};
        #pragma unroll
        for (int u = 0; u < 4; u++) {
            fma2(acc[u][0], qa[u], k0);
            fma2(acc[u][1], qa[u], k1);
        }
    }
    size_t pbase = (((size_t)((b * NHH + h) * HH + i)) * WW) * PLEN;
    #pragma unroll
    for (int u = 0; u < 4; u++) {
        int j = ty * 4 + u;
        float2 p0 = up2(acc[u][0]), p1 = up2(acc[u][1]);
        float4 o = make_float4(p0.x * SCALE, p0.y * SCALE, p1.x * SCALE, p1.y * SCALE);
        *(float4*)&g_P[pbase + (size_t)j * PLEN + tx * 4] = o;
    }
}

// =====================================================================
// Kernel 4: column logits (f32x2, 256 thr). block (j, h, b).
// =====================================================================
__global__ __launch_bounds__(256) void logits_col_kernel()
{
    int j = blockIdx.x, h = blockIdx.y, b = blockIdx.z;
    __shared__ float qs[64][64];
    __shared__ float ks[64][64];
    size_t base = ((size_t)(b * DQKV + h * DHH)) * HWN + j * HH;
    int t = threadIdx.x;
    #pragma unroll
    for (int r = 0; r < 16; r++) {
        int idx = r * 256 + t;
        int d = idx >> 6, ii = idx & 63;
        qs[d][ii] = g_QT[base + (size_t)d * HWN + ii];
        ks[d][ii] = g_KT[base + (size_t)d * HWN + ii];
    }
    __syncthreads();
    int tx = t & 15, ty = t >> 4;
    u64 acc[4][2];
    #pragma unroll
    for (int u = 0; u < 4; u++) { acc[u][0] = 0ull; acc[u][1] = 0ull; }
    #pragma unroll
    for (int d = 0; d < 64; d++) {
        float4 q4 = *(float4*)&qs[d][ty * 4];
        const u64* kp = (const u64*)&ks[d][tx * 4];
        u64 k0 = kp[0], k1 = kp[1];
        u64 qa[4] = {pk2(q4.x), pk2(q4.y), pk2(q4.z), pk2(q4.w)};
        #pragma unroll
        for (int u = 0; u < 4; u++) {
            fma2(acc[u][0], qa[u], k0);
            fma2(acc[u][1], qa[u], k1);
        }
    }
    size_t pre = ((size_t)((b * NHH + h) * HH) * WW + j) * PLEN + 64;
    #pragma unroll
    for (int u = 0; u < 4; u++) {
        int i = ty * 4 + u;
        float2 p0 = up2(acc[u][0]), p1 = up2(acc[u][1]);
        float4 o = make_float4(p0.x * SCALE, p0.y * SCALE, p1.x * SCALE, p1.y * SCALE);
        *(float4*)&g_P[pre + (size_t)i * (WW * PLEN) + tx * 4] = o;
    }
}

// =====================================================================
// Kernel 5: softmax over 128 logits per query, in place.
// =====================================================================
__global__ __launch_bounds__(256) void softmax_kernel()
{
    size_t row = (size_t)blockIdx.x * 8 + (threadIdx.x >> 5);
    int lane = threadIdx.x & 31;
    float* p = g_P + row * PLEN + lane * 4;
    float4 v = *(float4*)p;
    float m = fmaxf(fmaxf(v.x, v.y), fmaxf(v.z, v.w));
    #pragma unroll
    for (int o = 16; o; o >>= 1) m = fmaxf(m, __shfl_xor_sync(0xffffffffu, m, o));
    v.x = __expf(v.x - m); v.y = __expf(v.y - m);
    v.z = __expf(v.z - m); v.w = __expf(v.w - m);
    float s = v.x + v.y + v.z + v.w;
    #pragma unroll
    for (int o = 16; o; o >>= 1) s += __shfl_xor_sync(0xffffffffu, s, o);
    float inv = 1.0f / s;
    v.x *= inv; v.y *= inv; v.z *= inv; v.w *= inv;
    *(float4*)p = v;
}

// =====================================================================
// Kernel 6: row attention (f32x2). block (i,h,b).
// Stores a_w into g_A at [b][p=(i,j)][ch] layout (float4 over 4 ch).
// =====================================================================
__global__ __launch_bounds__(256) void attn_row_kernel()
{
    int i = blockIdx.x, h = blockIdx.y, b = blockIdx.z;
    __shared__ float vsT[64][68];
    __shared__ float psT[64][68];
    size_t vbase = ((size_t)(b * DQKV + h * DHH)) * HWN + i * WW;
    size_t pbase = (((size_t)((b * NHH + h) * HH + i)) * WW) * PLEN;
    int t = threadIdx.x;
    #pragma unroll
    for (int r = 0; r < 16; r++) {
        int idx = r * 256 + t;
        int a = idx >> 6, k = idx & 63;
        vsT[k][a] = g_V[vbase + (size_t)a * HWN + k];
        psT[k][a] = g_P[pbase + (size_t)a * PLEN + k];
    }
    __syncthreads();
    int tx = t & 15, ty = t >> 4;
    u64 acc[4][2];
    #pragma unroll
    for (int u = 0; u < 4; u++) { acc[u][0] = 0ull; acc[u][1] = 0ull; }
    #pragma unroll
    for (int k = 0; k < 64; k++) {
        float4 v4 = *(float4*)&vsT[k][ty * 4];
        const u64* pp = (const u64*)&psT[k][tx * 4];
        u64 p0 = pp[0], p1 = pp[1];
        u64 va[4] = {pk2(v4.x), pk2(v4.y), pk2(v4.z), pk2(v4.w)};
        #pragma unroll
        for (int u = 0; u < 4; u++) {
            fma2(acc[u][0], va[u], p0);
            fma2(acc[u][1], va[u], p1);
        }
    }
    // unpack acc: av[u=d'][c=j'] where d = ty*4+u, j = tx*4+c
    float av[4][4];
    #pragma unroll
    for (int u = 0; u < 4; u++) {
        float2 a0 = up2(acc[u][0]), a1 = up2(acc[u][1]);
        av[u][0] = a0.x; av[u][1] = a0.y; av[u][2] = a1.x; av[u][3] = a1.y;
    }
    int chb = h * DHH + ty * 4;
    #pragma unroll
    for (int cc = 0; cc < 4; cc++) {
        int p = i * WW + tx * 4 + cc;
        *(float4*)(g_A + ((size_t)b * HWN + p) * DQKV + chb) =
            make_float4(av[0][cc], av[1][cc], av[2][cc], av[3][cc]);
    }
}

// =====================================================================
// Kernel 7: column attention (f32x2). block (j,h,b).
// Stores a_h into g_AT at [b][p=(i,j)][ch] layout.
// =====================================================================
__global__ __launch_bounds__(256) void attn_col_kernel()
{
    int j = blockIdx.x, h = blockIdx.y, b = blockIdx.z;
    __shared__ float vsT[64][68];
    __shared__ float psT[64][68];
    size_t vbase = ((size_t)(b * DQKV + h * DHH)) * HWN + j * HH;
    size_t pcol  = ((size_t)((b * NHH + h) * HH) * WW + j) * PLEN + 64;
    int t = threadIdx.x;
    #pragma unroll
    for (int r = 0; r < 16; r++) {
        int idx = r * 256 + t;
        int a = idx >> 6, k = idx & 63;
        vsT[k][a] = g_VT[vbase + (size_t)a * HWN + k];
        psT[k][a] = g_P[pcol + (size_t)a * (WW * PLEN) + k];
    }
    __syncthreads();
    int tx = t & 15, ty = t >> 4;
    u64 acc[4][2];
    #pragma unroll
    for (int u = 0; u < 4; u++) { acc[u][0] = 0ull; acc[u][1] = 0ull; }
    #pragma unroll
    for (int k = 0; k < 64; k++) {
        float4 v4 = *(float4*)&vsT[k][ty * 4];
        const u64* pp = (const u64*)&psT[k][tx * 4];
        u64 p0 = pp[0], p1 = pp[1];
        u64 va[4] = {pk2(v4.x), pk2(v4.y), pk2(v4.z), pk2(v4.w)};
        #pragma unroll
        for (int u = 0; u < 4; u++) {
            fma2(acc[u][0], va[u], p0);
            fma2(acc[u][1], va[u], p1);
        }
    }
    float av[4][4];
    #pragma unroll
    for (int u = 0; u < 4; u++) {
        float2 a0 = up2(acc[u][0]), a1 = up2(acc[u][1]);
        av[u][0] = a0.x; av[u][1] = a0.y; av[u][2] = a1.x; av[u][3] = a1.y;
    }
    int chb = h * DHH + ty * 4;
    #pragma unroll
    for (int cc = 0; cc < 4; cc++) {
        int p = (tx * 4 + cc) * WW + j;    // i = tx*4+cc
        *(float4*)(g_AT + ((size_t)b * HWN + p) * DQKV + chb) =
            make_float4(av[0][cc], av[1][cc], av[2][cc], av[3][cc]);
    }
}

// =====================================================================
// Kernel 9: output projection + residual via mma.sync tf32.
// Block 128 ch x 128 p, K=512 in 16 chunks of 32.
// B-fill adds a_w + a_h from [b][p][ch] tensors (coalesced).
// =====================================================================
__global__ __launch_bounds__(256, 2) void proj_mma(
    const float* __restrict__ x, const float* __restrict__ Wo,
    const float* __restrict__ bo, float* __restrict__ out)
{
    int pT = blockIdx.x, mT = blockIdx.y, b = blockIdx.z;
    int mOff = mT * 128;

    __shared__ uint32_t As[128][36];
    __shared__ uint32_t Bs[128][36];

    int t = threadIdx.x, lane = t & 31, wid = t >> 5;
    int g = lane >> 2, tig = lane & 3;
    int wm = (wid >> 2) * 64, wn = (wid & 3) * 32;

    const float* a2w = g_A  + ((size_t)b * HWN + (size_t)pT * 128) * DQKV;
    const float* a2h = g_AT + ((size_t)b * HWN + (size_t)pT * 128) * DQKV;

    float c[4][4][4];
    #pragma unroll
    for (int mi = 0; mi < 4; mi++)
        #pragma unroll
        for (int ni = 0; ni < 4; ni++)
            #pragma unroll
            for (int e = 0; e < 4; e++) c[mi][ni][e] = 0.0f;

    for (int c0 = 0; c0 < 16; c0++) {
        int kBase = c0 * 32;
        #pragma unroll
        for (int r = 0; r < 4; r++) {
            int idx = r * 256 + t;
            int row = idx >> 3, q = idx & 7;
            int k4 = kBase + q * 4;
            float4 va = *(const float4*)(Wo + (size_t)(mOff + row) * DQKV + k4);
            As[row][q * 4 + 0] = f2tf32(va.x);
            As[row][q * 4 + 1] = f2tf32(va.y);
            As[row][q * 4 + 2] = f2tf32(va.z);
            As[row][q * 4 + 3] = f2tf32(va.w);
            float4 vb = *(const float4*)(a2w + (size_t)row * DQKV + k4);
            float4 vh = *(const float4*)(a2h + (size_t)row * DQKV + k4);
            Bs[row][q * 4 + 0] = f2tf32(vb.x + vh.x);
            Bs[row][q * 4 + 1] = f2tf32(vb.y + vh.y);
            Bs[row][q * 4 + 2] = f2tf32(vb.z + vh.z);
            Bs[row][q * 4 + 3] = f2tf32(vb.w + vh.w);
        }
        __syncthreads();
        #pragma unroll
        for (int ks = 0; ks < 4; ks++) {
            int kk = ks * 8;
            uint32_t a[4][4], bfr[4][2];
            #pragma unroll
            for (int mi = 0; mi < 4; mi++) {
                int row = wm + mi * 16 + g;
                a[mi][0] = As[row][kk + tig];
                a[mi][1] = As[row + 8][kk + tig];
                a[mi][2] = As[row][kk + tig + 4];
                a[mi][3] = As[row + 8][kk + tig + 4];
            }
            #pragma unroll
            for (int ni = 0; ni < 4; ni++) {
                int col = wn + ni * 8 + g;
                bfr[ni][0] = Bs[col][kk + tig];
                bfr[ni][1] = Bs[col][kk + tig + 4];
            }
            #pragma unroll
            for (int mi = 0; mi < 4; mi++)
                #pragma unroll
                for (int ni = 0; ni < 4; ni++)
                    mma_tf32(c[mi][ni], a[mi], bfr[ni]);
        }
        __syncthreads();
    }

    // epilogue: D[m=ch][n=p] + bias + residual x
    #pragma unroll
    for (int mi = 0; mi < 4; mi++) {
        int row0 = wm + mi * 16 + g;
        int ch0 = mOff + row0;
        float bi0 = bo[ch0];
        float bi1 = bo[ch0 + 8];
        size_t base0 = ((size_t)b * CC + ch0) * HWN + (size_t)pT * 128;
        size_t base1 = base0 + (size_t)8 * HWN;
        #pragma unroll
        for (int ni = 0; ni < 4; ni++) {
            int col = wn + ni * 8 + tig * 2;
            float2 x0 = *(const float2*)(x + base0 + col);
            float2 x1 = *(const float2*)(x + base1 + col);
            float2 v0 = make_float2(c[mi][ni][0] + bi0 + x0.x,
                                    c[mi][ni][1] + bi0 + x0.y);
            float2 v1 = make_float2(c[mi][ni][2] + bi1 + x1.x,
                                    c[mi][ni][3] + bi1 + x1.y);
            *(float2*)(out + base0 + col) = v0;
            *(float2*)(out + base1 + col) = v1;
        }
    }
}

// =====================================================================
extern "C" void kernel_launch(void* const* d_in, const int* in_sizes, int n_in,
                              void* d_out, int out_size)
{
    const float* x   = (const float*)d_in[0];
    const float* pos = (const float*)d_in[1];
    const float* Wk  = (const float*)d_in[2];
    const float* bk  = (const float*)d_in[3];
    const float* Wq  = (const float*)d_in[4];
    const float* bq  = (const float*)d_in[5];
    const float* Wv  = (const float*)d_in[6];
    const float* bv  = (const float*)d_in[7];
    const float* Wo  = (const float*)d_in[8];
    const float* bo  = (const float*)d_in[9];
    float* out = (float*)d_out;

    xpose_x<<<dim3(64, 5, BB), 256>>>(x, pos);
    qkv_mma<<<dim3(32, 12, BB), 256>>>(Wq, bq, Wk, bk, Wv, bv);
    transpose3_kernel<<<dim3(BB * DQKV, 3), 256>>>();
    logits_row_kernel<<<dim3(HH, NHH, BB), 256>>>();
    logits_col_kernel<<<dim3(WW, NHH, BB), 256>>>();
    softmax_kernel<<<65536, 256>>>();
    attn_row_kernel<<<dim3(HH, NHH, BB), 256>>>();
    attn_col_kernel<<<dim3(WW, NHH, BB), 256>>>();
    proj_mma<<<dim3(32, 2, BB), 256>>>(x, Wo, bo, out);
}